// round 7
// baseline (speedup 1.0000x reference)
#include <cuda_runtime.h>
#include <mma.h>
#include <math.h>

using namespace nvcuda;

#define Bb 2
#define Nn 2048
#define MM_ 2048
#define Dd 1024
#define Hh 8
#define DHd 64
#define INNERi 512
#define FFDf 4096

// ---------------- scratch (device globals; no cudaMalloc allowed) ----------
__device__ __align__(256) float g_xn [Bb*Nn*Dd];
__device__ __align__(256) float g_cn [Bb*MM_*Dd];
__device__ __align__(256) float g_qk [Bb*Nn*INNERi];
__device__ __align__(256) float g_v  [Bb*Nn*INNERi];
__device__ __align__(256) float g_cqk[Bb*MM_*INNERi];
__device__ __align__(256) float g_cv [Bb*MM_*INNERi];
__device__ __align__(256) float g_sim  [Bb*Hh*Nn*MM_];
__device__ __align__(256) float g_attn [Bb*Hh*Nn*MM_];
__device__ __align__(256) float g_cattn[Bb*Hh*Nn*MM_];
__device__ __align__(256) float g_out [Bb*Nn*INNERi];
__device__ __align__(256) float g_cout[Bb*MM_*INNERi];
__device__ __align__(256) float g_x1  [Bb*Nn*Dd];
__device__ __align__(256) float g_c1  [Bb*MM_*Dd];
__device__ __align__(256) float g_h   [Bb*Nn*FFDf];
__device__ __align__(256) float g_wr [19922944];   // tf32-rounded weights
__device__ int   g_mask_mode;   // 0 = u8/bool, 1 = int32, 2 = float32

// rounded-weight offsets in g_wr
#define OFF_WQK   0L
#define OFF_WV    524288L
#define OFF_WCQK  1048576L
#define OFF_WCV   1572864L
#define OFF_WOUT  2097152L
#define OFF_WCOUT 2621440L
#define OFF_FFW1  3145728L
#define OFF_FFW2  7340032L
#define OFF_CFFW1 11534336L
#define OFF_CFFW2 15728640L

__device__ __forceinline__ float tf32r(float x)
{
    float r;
    asm("cvt.rna.tf32.f32 %0, %1;" : "=f"(r) : "f"(x));
    return r;
}

// ---------------- tf32 rounding copy (weights) ------------------------------
__global__ __launch_bounds__(256)
void tf32_round_k(const float4* __restrict__ in, float4* __restrict__ out, int n4)
{
    for (int i = blockIdx.x * 256 + threadIdx.x; i < n4; i += gridDim.x * 256) {
        float4 v = in[i];
        v.x = tf32r(v.x); v.y = tf32r(v.y);
        v.z = tf32r(v.z); v.w = tf32r(v.w);
        out[i] = v;
    }
}

// ---------------- mask dtype detection ------------------------------------
__global__ void detect_mask_mode(const float* __restrict__ fp, int n4)
{
    __shared__ int okf_s, oki_s;
    if (threadIdx.x == 0) { okf_s = 1; oki_s = 1; }
    __syncthreads();
    const int* ip = (const int*)fp;
    bool okf = true, oki = true;
    for (int i = threadIdx.x; i < n4; i += 256) {
        float fv = fp[i]; okf = okf && (fv == 0.f || fv == 1.f);
        int   iv = ip[i]; oki = oki && (iv == 0 || iv == 1);
    }
    if (!okf) atomicAnd(&okf_s, 0);
    if (!oki) atomicAnd(&oki_s, 0);
    __syncthreads();
    if (threadIdx.x == 0) g_mask_mode = okf_s ? 2 : (oki_s ? 1 : 0);
}

__device__ __forceinline__ bool mask_at(const void* m, int i, int mode)
{
    if (mode == 1) return ((const int*)m)[i] != 0;
    if (mode == 2) return ((const float*)m)[i] != 0.f;
    return ((const unsigned char*)m)[i] != 0;
}

// ---------------- LayerNorm (output rounded to tf32) -----------------------
__global__ __launch_bounds__(256)
void ln_k(const float* __restrict__ in, const float* __restrict__ g,
          const float* __restrict__ b, float* __restrict__ out, int cols)
{
    __shared__ float r1[256], r2[256];
    long row = blockIdx.x;
    const float* p = in + row * cols;
    float* o = out + row * cols;
    int tid = threadIdx.x;
    float s = 0.f, s2 = 0.f;
    for (int c = tid; c < cols; c += 256) { float v = p[c]; s += v; s2 += v * v; }
    r1[tid] = s; r2[tid] = s2; __syncthreads();
    for (int st = 128; st > 0; st >>= 1) {
        if (tid < st) { r1[tid] += r1[tid + st]; r2[tid] += r2[tid + st]; }
        __syncthreads();
    }
    float mu  = r1[0] / cols;
    float var = r2[0] / cols - mu * mu;
    float inv = rsqrtf(var + 1e-5f);
    for (int c = tid; c < cols; c += 256)
        o[c] = tf32r((p[c] - mu) * inv * g[c] + b[c]);
}

// ---------------- Row softmax (output rounded to tf32) ---------------------
__global__ __launch_bounds__(256)
void softmax_row(const float* __restrict__ sim, float* __restrict__ attn,
                 const void* __restrict__ mask,
                 const void* __restrict__ cmask)
{
    __shared__ float buf[MM_];
    __shared__ float red[256];
    int mode = g_mask_mode;
    long row = blockIdx.x;             // (b*H + h)*N + i
    int i  = (int)(row % Nn);
    int bh = (int)(row / Nn);
    int b  = bh / Hh;
    const float* src = sim  + row * (long)MM_;
    float*       dst = attn + row * (long)MM_;
    int tid = threadIdx.x;
    bool mi = mask_at(mask, b * Nn + i, mode);

    float lmax = -3.402823466e38f;
    for (int j = tid; j < MM_; j += 256) {
        bool mj = mask_at(cmask, b * MM_ + j, mode);
        float vv = (mi && mj) ? src[j] : -3.402823466e38f;
        buf[j] = vv;
        lmax = fmaxf(lmax, vv);
    }
    red[tid] = lmax; __syncthreads();
    for (int s = 128; s > 0; s >>= 1) {
        if (tid < s) red[tid] = fmaxf(red[tid], red[tid + s]);
        __syncthreads();
    }
    float rmax = red[0]; __syncthreads();
    float lsum = 0.f;
    for (int j = tid; j < MM_; j += 256) {
        float e = expf(buf[j] - rmax);
        buf[j] = e; lsum += e;
    }
    red[tid] = lsum; __syncthreads();
    for (int s = 128; s > 0; s >>= 1) {
        if (tid < s) red[tid] += red[tid + s];
        __syncthreads();
    }
    float inv = 1.f / red[0];
    for (int j = tid; j < MM_; j += 256) dst[j] = tf32r(buf[j] * inv);
}

// ---------------- Column softmax (output rounded to tf32) ------------------
__global__ __launch_bounds__(256)
void softmax_col(const float* __restrict__ sim, float* __restrict__ cattn,
                 const void* __restrict__ mask,
                 const void* __restrict__ cmask)
{
    __shared__ float sm[8][32], ss[8][32];
    int mode = g_mask_mode;
    int z = blockIdx.y;                // b*H + h
    int b = z / Hh;
    int c = threadIdx.x & 31;
    int g = threadIdx.x >> 5;
    int j = blockIdx.x * 32 + c;
    const float* base = sim   + (long)z * Nn * MM_;
    float*       outb = cattn + (long)z * Nn * MM_;
    bool mj = mask_at(cmask, b * MM_ + j, mode);

    float m = -3.402823466e38f, s = 0.f;
    for (int i = g; i < Nn; i += 8) {
        bool mi = mask_at(mask, b * Nn + i, mode);
        float vv = (mj && mi) ? base[(long)i * MM_ + j] : -3.402823466e38f;
        if (vv > m) { s = s * expf(m - vv) + 1.f; m = vv; }
        else        { s += expf(vv - m); }
    }
    sm[g][c] = m; ss[g][c] = s; __syncthreads();
    if (g == 0) {
        float Mloc = sm[0][c], Sloc = ss[0][c];
        #pragma unroll
        for (int t = 1; t < 8; t++) {
            float mt = sm[t][c], st = ss[t][c];
            float nm = fmaxf(Mloc, mt);
            Sloc = Sloc * expf(Mloc - nm) + st * expf(mt - nm);
            Mloc = nm;
        }
        sm[0][c] = Mloc; ss[0][c] = 1.f / Sloc;
    }
    __syncthreads();
    float Mg = sm[0][c], inv = ss[0][c];
    for (int i = g; i < Nn; i += 8) {
        bool mi = mask_at(mask, b * Nn + i, mode);
        float vv = (mj && mi) ? base[(long)i * MM_ + j] : -3.402823466e38f;
        outb[(long)i * MM_ + j] = tf32r(expf(vv - Mg) * inv);
    }
}

// ---------------- cp.async helpers -----------------------------------------
__device__ __forceinline__ void cpa16(float* dst, const float* src)
{
    unsigned d = (unsigned)__cvta_generic_to_shared(dst);
    asm volatile("cp.async.cg.shared.global [%0], [%1], 16;\n" :: "r"(d), "l"(src));
}

// ---------------- TF32 WMMA GEMM, 3-stage cp.async pipeline ----------------
// ALL operands are pre-rounded to tf32 by their producers, so the hot loop
// issues NO cvt instructions (HW truncation of rounded values is identity).
// Block tile BMxBN, K-tile 32, 256 threads (8 warps), 2 CTAs/SM, one
// __syncthreads per k-tile.
// EPI: 0 = alpha (+opt tf32-round) direct frag store;
//      2 = bias+residual; 3 = bias+exact GELU (+opt tf32-round).
template<int BM, int BN, bool AC, bool BC, int EPI, bool RND>
__global__ __launch_bounds__(256, 2)
void gemm2(const float* __restrict__ A, int lda, long aO, long aI,
           const float* __restrict__ Bm, int ldb, long bO, long bI,
           float* __restrict__ C, int ldc, long cO, long cI,
           const float* __restrict__ bias,
           const float* __restrict__ res, int ldr,
           int K, float alpha, int HHd)
{
    constexpr int BK   = 32;
    constexpr int NST  = 3;
    constexpr int LDAS = AC ? BM + 4 : BK + 4;
    constexpr int AEL  = AC ? BK * LDAS : BM * LDAS;
    constexpr int LDBS = BC ? BK + 4 : BN + 4;
    constexpr int BEL  = BC ? BN * LDBS : BK * LDBS;
    constexpr int WRM  = (BN == 128) ? 2 : 4;
    constexpr int WRN  = 8 / WRM;
    constexpr int TM   = BM / WRM;
    constexpr int TN   = BN / WRN;
    constexpr int FM   = TM / 16;
    constexpr int FN   = TN / 16;
    constexpr int LDCS = BN + 4;

    extern __shared__ float sm_[];
    float* sA = sm_;
    float* sB = sm_ + NST * AEL;
    float* sC = sm_;   // epilogue staging aliases pipeline buffers

    int z  = blockIdx.z;
    int zo = z / HHd, zi = z % HHd;
    A  += (long)zo * aO + (long)zi * aI;
    Bm += (long)zo * bO + (long)zi * bI;
    C  += (long)zo * cO + (long)zi * cI;

    int m0 = blockIdx.y * BM;
    int n0 = blockIdx.x * BN;
    int tid  = threadIdx.x;
    int warp = tid >> 5;
    int wm0 = (warp % WRM) * TM;
    int wn0 = (warp / WRM) * TN;

    auto load_stage = [&](int s, int kt) {
        float* sAs = sA + s * AEL;
        float* sBs = sB + s * BEL;
        if (!AC) {
            constexpr int IT = (BM * (BK / 4)) / 256;
            #pragma unroll
            for (int t = 0; t < IT; t++) {
                int idx = t * 256 + tid;
                int r = idx >> 3, c = idx & 7;
                cpa16(sAs + r * LDAS + c * 4,
                      A + (long)(m0 + r) * lda + kt + c * 4);
            }
        } else {
            constexpr int PR = BM / 4;
            constexpr int IT = (BK * PR) / 256;
            #pragma unroll
            for (int t = 0; t < IT; t++) {
                int idx = t * 256 + tid;
                int k = idx / PR, mc = idx % PR;
                cpa16(sAs + k * LDAS + mc * 4,
                      A + (long)(kt + k) * lda + m0 + mc * 4);
            }
        }
        if (!BC) {
            constexpr int PR = BN / 4;
            constexpr int IT = (BK * PR) / 256;
            #pragma unroll
            for (int t = 0; t < IT; t++) {
                int idx = t * 256 + tid;
                int r = idx / PR, c = idx % PR;
                cpa16(sBs + r * LDBS + c * 4,
                      Bm + (long)(kt + r) * ldb + n0 + c * 4);
            }
        } else {
            constexpr int IT = (BN * (BK / 4)) / 256;
            #pragma unroll
            for (int t = 0; t < IT; t++) {
                int idx = t * 256 + tid;
                int n = idx >> 3, c = idx & 7;
                cpa16(sBs + n * LDBS + c * 4,
                      Bm + (long)(n0 + n) * ldb + kt + c * 4);
            }
        }
        asm volatile("cp.async.commit_group;\n");
    };

    using ALay = typename std::conditional<AC, wmma::col_major, wmma::row_major>::type;
    using BLay = typename std::conditional<BC, wmma::col_major, wmma::row_major>::type;

    wmma::fragment<wmma::accumulator, 16, 16, 8, float> fc[FM][FN];
    #pragma unroll
    for (int i = 0; i < FM; i++)
        #pragma unroll
        for (int j = 0; j < FN; j++)
            wmma::fill_fragment(fc[i][j], 0.f);

    int T = K / BK;
    load_stage(0, 0);
    if (T > 1) load_stage(1, BK);

    for (int kt = 0; kt < T; kt++) {
        if (kt + 1 < T) asm volatile("cp.async.wait_group 1;\n");
        else            asm volatile("cp.async.wait_group 0;\n");
        __syncthreads();
        if (kt + 2 < T) load_stage((kt + 2) % NST, (kt + 2) * BK);

        int s = kt % NST;
        const float* sAs = sA + s * AEL;
        const float* sBs = sB + s * BEL;

        #pragma unroll
        for (int kk = 0; kk < BK; kk += 8) {
            wmma::fragment<wmma::matrix_a, 16, 16, 8, wmma::precision::tf32, ALay> fa[FM];
            wmma::fragment<wmma::matrix_b, 16, 16, 8, wmma::precision::tf32, BLay> fb[FN];
            #pragma unroll
            for (int i = 0; i < FM; i++) {
                const float* ap = AC ? (sAs + kk * LDAS + wm0 + i * 16)
                                     : (sAs + (wm0 + i * 16) * LDAS + kk);
                wmma::load_matrix_sync(fa[i], ap, LDAS);
            }
            #pragma unroll
            for (int j = 0; j < FN; j++) {
                const float* bp = BC ? (sBs + (wn0 + j * 16) * LDBS + kk)
                                     : (sBs + kk * LDBS + wn0 + j * 16);
                wmma::load_matrix_sync(fb[j], bp, LDBS);
            }
            #pragma unroll
            for (int i = 0; i < FM; i++)
                #pragma unroll
                for (int j = 0; j < FN; j++)
                    wmma::mma_sync(fc[i][j], fa[i], fb[j], fc[i][j]);
        }
    }

    if (EPI == 0) {
        #pragma unroll
        for (int i = 0; i < FM; i++)
            #pragma unroll
            for (int j = 0; j < FN; j++) {
                #pragma unroll
                for (int t = 0; t < fc[i][j].num_elements; t++) {
                    float vv = fc[i][j].x[t] * alpha;
                    fc[i][j].x[t] = RND ? tf32r(vv) : vv;
                }
                wmma::store_matrix_sync(
                    C + (long)(m0 + wm0 + i * 16) * ldc + n0 + wn0 + j * 16,
                    fc[i][j], ldc, wmma::mem_row_major);
            }
    } else {
        __syncthreads();   // all warps done with pipeline smem before aliasing
        #pragma unroll
        for (int i = 0; i < FM; i++)
            #pragma unroll
            for (int j = 0; j < FN; j++)
                wmma::store_matrix_sync(sC + (wm0 + i * 16) * LDCS + wn0 + j * 16,
                                        fc[i][j], LDCS, wmma::mem_row_major);
        __syncthreads();
        constexpr int NB4 = BN / 4;
        for (int idx = tid; idx < BM * NB4; idx += 256) {
            int r = idx / NB4, c4 = (idx % NB4) * 4;
            int gm = m0 + r, gn = n0 + c4;
            float4 vv = *(const float4*)(sC + r * LDCS + c4);
            float4 bb = *(const float4*)(bias + gn);
            if (EPI == 2) {
                float4 rr = *(const float4*)(res + (long)gm * ldr + gn);
                vv.x += bb.x + rr.x; vv.y += bb.y + rr.y;
                vv.z += bb.z + rr.z; vv.w += bb.w + rr.w;
            } else {
                vv.x += bb.x; vv.y += bb.y; vv.z += bb.z; vv.w += bb.w;
                vv.x = 0.5f * vv.x * (1.f + erff(vv.x * 0.7071067811865476f));
                vv.y = 0.5f * vv.y * (1.f + erff(vv.y * 0.7071067811865476f));
                vv.z = 0.5f * vv.z * (1.f + erff(vv.z * 0.7071067811865476f));
                vv.w = 0.5f * vv.w * (1.f + erff(vv.w * 0.7071067811865476f));
                if (RND) {
                    vv.x = tf32r(vv.x); vv.y = tf32r(vv.y);
                    vv.z = tf32r(vv.z); vv.w = tf32r(vv.w);
                }
            }
            *(float4*)(C + (long)gm * ldc + gn) = vv;
        }
    }
}

// host-side smem size (mirrors kernel constexprs)
static constexpr size_t smemb(int BM, int BN, bool AC, bool BC, int EPI)
{
    int LDAS = AC ? BM + 4 : 36;
    int AEL  = AC ? 32 * LDAS : BM * LDAS;
    int LDBS = BC ? 36 : BN + 4;
    int BEL  = BC ? BN * LDBS : 32 * LDBS;
    int pipe = 3 * (AEL + BEL);
    int epi  = EPI ? BM * (BN + 4) : 0;
    return 4u * (size_t)(pipe > epi ? pipe : epi);
}

#define LAUNCH_GEMM(BM, BN, AC, BC, EPI, RND, grid, ...)                        \
    do {                                                                        \
        auto kfn = gemm2<BM, BN, AC, BC, EPI, RND>;                             \
        size_t smb = smemb(BM, BN, AC, BC, EPI);                                \
        cudaFuncSetAttribute(kfn, cudaFuncAttributeMaxDynamicSharedMemorySize,  \
                             (int)smb);                                         \
        kfn<<<grid, 256, smb>>>(__VA_ARGS__);                                   \
    } while (0)

// ---------------- host ----------------------------------------------------
extern "C" void kernel_launch(void* const* d_in, const int* in_sizes, int n_in,
                              void* d_out, int out_size)
{
    (void)in_sizes; (void)n_in; (void)out_size;
    const float* x      = (const float*)d_in[0];
    const float* ctx    = (const float*)d_in[1];
    const void*  mask   = d_in[2];
    const void*  cmask  = d_in[3];
    const float* ln_x_g = (const float*)d_in[4];
    const float* ln_x_b = (const float*)d_in[5];
    const float* ln_c_g = (const float*)d_in[6];
    const float* ln_c_b = (const float*)d_in[7];
    const float* W_qk   = (const float*)d_in[8];
    const float* W_v    = (const float*)d_in[9];
    const float* Wc_qk  = (const float*)d_in[10];
    const float* Wc_v   = (const float*)d_in[11];
    const float* W_out  = (const float*)d_in[12];
    const float* b_out  = (const float*)d_in[13];
    const float* Wc_out = (const float*)d_in[14];
    const float* bc_out = (const float*)d_in[15];
    const float* ff_g   = (const float*)d_in[16];
    const float* ff_b   = (const float*)d_in[17];
    const float* ff_w1  = (const float*)d_in[18];
    const float* ff_b1  = (const float*)d_in[19];
    const float* ff_w2  = (const float*)d_in[20];
    const float* ff_b2  = (const float*)d_in[21];
    const float* cff_g  = (const float*)d_in[22];
    const float* cff_b  = (const float*)d_in[23];
    const float* cff_w1 = (const float*)d_in[24];
    const float* cff_b1 = (const float*)d_in[25];
    const float* cff_w2 = (const float*)d_in[26];
    const float* cff_b2 = (const float*)d_in[27];
    float* outp = (float*)d_out;

    float *xn, *cn, *qk, *v, *cqk, *cv, *sim, *attn, *cattn, *out, *cout, *x1, *c1, *hbuf, *wr;
    cudaGetSymbolAddress((void**)&xn,    g_xn);
    cudaGetSymbolAddress((void**)&cn,    g_cn);
    cudaGetSymbolAddress((void**)&qk,    g_qk);
    cudaGetSymbolAddress((void**)&v,     g_v);
    cudaGetSymbolAddress((void**)&cqk,   g_cqk);
    cudaGetSymbolAddress((void**)&cv,    g_cv);
    cudaGetSymbolAddress((void**)&sim,   g_sim);
    cudaGetSymbolAddress((void**)&attn,  g_attn);
    cudaGetSymbolAddress((void**)&cattn, g_cattn);
    cudaGetSymbolAddress((void**)&out,   g_out);
    cudaGetSymbolAddress((void**)&cout,  g_cout);
    cudaGetSymbolAddress((void**)&x1,    g_x1);
    cudaGetSymbolAddress((void**)&c1,    g_c1);
    cudaGetSymbolAddress((void**)&hbuf,  g_h);
    cudaGetSymbolAddress((void**)&wr,    g_wr);

    const float SCALE = 0.125f;   // DH^-0.5 = 64^-0.5

    // 0) detect mask dtype; round all weights to tf32 once
    detect_mask_mode<<<1, 256>>>((const float*)mask, (Bb * Nn) / 4);
    #define RW(src, off, n) \
        tf32_round_k<<<512, 256>>>((const float4*)(src), (float4*)(wr + (off)), (n) / 4)
    RW(W_qk,   OFF_WQK,   Dd * INNERi);
    RW(W_v,    OFF_WV,    Dd * INNERi);
    RW(Wc_qk,  OFF_WCQK,  Dd * INNERi);
    RW(Wc_v,   OFF_WCV,   Dd * INNERi);
    RW(W_out,  OFF_WOUT,  INNERi * Dd);
    RW(Wc_out, OFF_WCOUT, INNERi * Dd);
    RW(ff_w1,  OFF_FFW1,  Dd * FFDf);
    RW(ff_w2,  OFF_FFW2,  FFDf * Dd);
    RW(cff_w1, OFF_CFFW1, Dd * FFDf);
    RW(cff_w2, OFF_CFFW2, FFDf * Dd);
    #undef RW

    // 1) pre-norm (outputs tf32-rounded)
    ln_k<<<Bb * Nn,  256>>>(x,   ln_x_g, ln_x_b, xn, Dd);
    ln_k<<<Bb * MM_, 256>>>(ctx, ln_c_g, ln_c_b, cn, Dd);

    // 2) projections (outputs tf32-rounded)
    LAUNCH_GEMM(64, 128, false, false, 0, true,
                dim3(INNERi / 128, Bb * Nn / 64, 1),
                xn, Dd, 0, 0, wr + OFF_WQK, INNERi, 0, 0, qk, INNERi, 0, 0,
                nullptr, nullptr, 0, Dd, 1.f, 1);
    LAUNCH_GEMM(64, 128, false, false, 0, true,
                dim3(INNERi / 128, Bb * Nn / 64, 1),
                xn, Dd, 0, 0, wr + OFF_WV, INNERi, 0, 0, v, INNERi, 0, 0,
                nullptr, nullptr, 0, Dd, 1.f, 1);
    LAUNCH_GEMM(64, 128, false, false, 0, true,
                dim3(INNERi / 128, Bb * MM_ / 64, 1),
                cn, Dd, 0, 0, wr + OFF_WCQK, INNERi, 0, 0, cqk, INNERi, 0, 0,
                nullptr, nullptr, 0, Dd, 1.f, 1);
    LAUNCH_GEMM(64, 128, false, false, 0, true,
                dim3(INNERi / 128, Bb * MM_ / 64, 1),
                cn, Dd, 0, 0, wr + OFF_WCV, INNERi, 0, 0, cv, INNERi, 0, 0,
                nullptr, nullptr, 0, Dd, 1.f, 1);

    // 3) sim[b,h] = qk[b,:,h,:] @ cqk[b,:,h,:]^T * SCALE  (plain f32 output)
    LAUNCH_GEMM(128, 128, false, true, 0, false,
                dim3(MM_ / 128, Nn / 128, Bb * Hh),
                qk,  INNERi, (long)Nn  * INNERi, DHd,
                cqk, INNERi, (long)MM_ * INNERi, DHd,
                sim, MM_,    (long)Hh * Nn * MM_, (long)Nn * MM_,
                nullptr, nullptr, 0, DHd, SCALE, Hh);

    // 4) dual softmax (outputs tf32-rounded)
    softmax_row<<<Bb * Hh * Nn, 256>>>(sim, attn, mask, cmask);
    softmax_col<<<dim3(MM_ / 32, Bb * Hh), 256>>>(sim, cattn, mask, cmask);

    // 5) out = attn @ cv ;  cout = cattn^T @ v  (outputs tf32-rounded)
    LAUNCH_GEMM(128, 64, false, false, 0, true,
                dim3(1, Nn / 128, Bb * Hh),
                attn, MM_,   (long)Hh * Nn * MM_, (long)Nn * MM_,
                cv,  INNERi, (long)MM_ * INNERi, DHd,
                out, INNERi, (long)Nn  * INNERi, DHd,
                nullptr, nullptr, 0, MM_, 1.f, Hh);
    LAUNCH_GEMM(128, 64, true, false, 0, true,
                dim3(1, MM_ / 128, Bb * Hh),
                cattn, MM_,  (long)Hh * Nn * MM_, (long)Nn * MM_,
                v,   INNERi, (long)Nn  * INNERi, DHd,
                cout, INNERi, (long)MM_ * INNERi, DHd,
                nullptr, nullptr, 0, Nn, 1.f, Hh);

    // 6) output projection + residual (full f32 output)
    LAUNCH_GEMM(128, 128, false, false, 2, false,
                dim3(Dd / 128, Bb * Nn / 128, 1),
                out, INNERi, 0, 0, wr + OFF_WOUT, Dd, 0, 0, x1, Dd, 0, 0,
                b_out, x, Dd, INNERi, 1.f, 1);
    LAUNCH_GEMM(128, 128, false, false, 2, false,
                dim3(Dd / 128, Bb * MM_ / 128, 1),
                cout, INNERi, 0, 0, wr + OFF_WCOUT, Dd, 0, 0, c1, Dd, 0, 0,
                bc_out, ctx, Dd, INNERi, 1.f, 1);

    // 7) FFN (x side) -> d_out[0 : B*N*D)
    ln_k<<<Bb * Nn, 256>>>(x1, ff_g, ff_b, xn, Dd);
    LAUNCH_GEMM(128, 128, false, false, 3, true,
                dim3(FFDf / 128, Bb * Nn / 128, 1),
                xn, Dd, 0, 0, wr + OFF_FFW1, FFDf, 0, 0, hbuf, FFDf, 0, 0,
                ff_b1, nullptr, 0, Dd, 1.f, 1);
    LAUNCH_GEMM(128, 128, false, false, 2, false,
                dim3(Dd / 128, Bb * Nn / 128, 1),
                hbuf, FFDf, 0, 0, wr + OFF_FFW2, Dd, 0, 0, outp, Dd, 0, 0,
                ff_b2, x1, Dd, FFDf, 1.f, 1);

    // 8) FFN (context side) -> d_out[B*N*D : 2*B*N*D)
    ln_k<<<Bb * MM_, 256>>>(c1, cff_g, cff_b, cn, Dd);
    LAUNCH_GEMM(128, 128, false, false, 3, true,
                dim3(FFDf / 128, Bb * MM_ / 128, 1),
                cn, Dd, 0, 0, wr + OFF_CFFW1, FFDf, 0, 0, hbuf, FFDf, 0, 0,
                cff_b1, nullptr, 0, Dd, 1.f, 1);
    LAUNCH_GEMM(128, 128, false, false, 2, false,
                dim3(Dd / 128, Bb * MM_ / 128, 1),
                hbuf, FFDf, 0, 0, wr + OFF_CFFW2, Dd, 0, 0, outp + (long)Bb * Nn * Dd, Dd, 0, 0,
                cff_b2, c1, Dd, FFDf, 1.f, 1);
}

// round 9
// speedup vs baseline: 1.3336x; 1.3336x over previous
#include <cuda_runtime.h>
#include <cuda_bf16.h>
#include <mma.h>
#include <math.h>
#include <cstdint>

using namespace nvcuda;
typedef __nv_bfloat16 bf16;

#define Bb 2
#define Nn 2048
#define MM_ 2048
#define Dd 1024
#define Hh 8
#define DHd 64
#define INNERi 512
#define FFDf 4096

// ---------------- scratch ----------------------------------------------------
__device__ __align__(256) float g_sim  [Bb*Hh*Nn*MM_];
__device__ __align__(256) float g_x1  [Bb*Nn*Dd];
__device__ __align__(256) float g_c1  [Bb*MM_*Dd];
__device__ __align__(256) bf16 g_attn [Bb*Hh*Nn*MM_];
__device__ __align__(256) bf16 g_cattn[Bb*Hh*Nn*MM_];
__device__ __align__(256) bf16 g_qk [Bb*Nn*INNERi];
__device__ __align__(256) bf16 g_v  [Bb*Nn*INNERi];
__device__ __align__(256) bf16 g_cqk[Bb*MM_*INNERi];
__device__ __align__(256) bf16 g_cv [Bb*MM_*INNERi];
__device__ __align__(256) bf16 g_out [Bb*Nn*INNERi];
__device__ __align__(256) bf16 g_cout[Bb*MM_*INNERi];
__device__ __align__(256) bf16 g_xnh[Bb*Nn*Dd];
__device__ __align__(256) bf16 g_xnl[Bb*Nn*Dd];
__device__ __align__(256) bf16 g_cnh[Bb*MM_*Dd];
__device__ __align__(256) bf16 g_cnl[Bb*MM_*Dd];
__device__ __align__(256) bf16 g_hh[Bb*Nn*FFDf];
__device__ __align__(256) bf16 g_hl[Bb*Nn*FFDf];
__device__ __align__(256) bf16 g_wph[4*INNERi*Dd];
__device__ __align__(256) bf16 g_woh[2*Dd*INNERi];
__device__ __align__(256) bf16 g_f1h[2*FFDf*Dd];
__device__ __align__(256) bf16 g_f1l[2*FFDf*Dd];
__device__ __align__(256) bf16 g_f2h[2*Dd*FFDf];
__device__ __align__(256) bf16 g_f2l[2*Dd*FFDf];
__device__ int g_mask_mode;

// ---------------- mask detection ---------------------------------------------
__global__ void detect_mask_mode(const float* __restrict__ fp, int n4)
{
    __shared__ int okf_s, oki_s;
    if (threadIdx.x == 0) { okf_s = 1; oki_s = 1; }
    __syncthreads();
    const int* ip = (const int*)fp;
    bool okf = true, oki = true;
    for (int i = threadIdx.x; i < n4; i += 256) {
        float fv = fp[i]; okf = okf && (fv == 0.f || fv == 1.f);
        int   iv = ip[i]; oki = oki && (iv == 0 || iv == 1);
    }
    if (!okf) atomicAnd(&okf_s, 0);
    if (!oki) atomicAnd(&oki_s, 0);
    __syncthreads();
    if (threadIdx.x == 0) g_mask_mode = okf_s ? 2 : (oki_s ? 1 : 0);
}
__device__ __forceinline__ bool mask_at(const void* m, int i, int mode)
{
    if (mode == 1) return ((const int*)m)[i] != 0;
    if (mode == 2) return ((const float*)m)[i] != 0.f;
    return ((const unsigned char*)m)[i] != 0;
}

// ---------------- LayerNorm -> bf16 hi/lo ------------------------------------
__global__ __launch_bounds__(256)
void ln_bf(const float* __restrict__ in, const float* __restrict__ g,
           const float* __restrict__ b, bf16* __restrict__ oh,
           bf16* __restrict__ ol, int cols)
{
    __shared__ float r1[256], r2[256];
    long row = blockIdx.x;
    const float* p = in + row * cols;
    bf16* ph = oh + row * cols;
    bf16* pl = ol + row * cols;
    int tid = threadIdx.x;
    float s = 0.f, s2 = 0.f;
    for (int c = tid; c < cols; c += 256) { float v = p[c]; s += v; s2 += v * v; }
    r1[tid] = s; r2[tid] = s2; __syncthreads();
    for (int st = 128; st > 0; st >>= 1) {
        if (tid < st) { r1[tid] += r1[tid + st]; r2[tid] += r2[tid + st]; }
        __syncthreads();
    }
    float mu  = r1[0] / cols;
    float var = r2[0] / cols - mu * mu;
    float inv = rsqrtf(var + 1e-5f);
    for (int c = tid; c < cols; c += 256) {
        float y = (p[c] - mu) * inv * g[c] + b[c];
        bf16 hv = __float2bfloat16(y);
        ph[c] = hv;
        pl[c] = __float2bfloat16(y - __bfloat162float(hv));
    }
}

// ---------------- dual softmax (bf16 outputs) ---------------------------------
__global__ __launch_bounds__(256)
void softmax_row(const float* __restrict__ sim, bf16* __restrict__ attn,
                 const void* __restrict__ mask, const void* __restrict__ cmask)
{
    __shared__ float buf[MM_];
    __shared__ float red[256];
    int mode = g_mask_mode;
    long row = blockIdx.x;
    int i = (int)(row % Nn), bh = (int)(row / Nn), b = bh / Hh;
    const float* src = sim  + row * (long)MM_;
    bf16*        dst = attn + row * (long)MM_;
    int tid = threadIdx.x;
    bool mi = mask_at(mask, b * Nn + i, mode);
    float lmax = -3.402823466e38f;
    for (int j = tid; j < MM_; j += 256) {
        bool mj = mask_at(cmask, b * MM_ + j, mode);
        float vv = (mi && mj) ? src[j] : -3.402823466e38f;
        buf[j] = vv; lmax = fmaxf(lmax, vv);
    }
    red[tid] = lmax; __syncthreads();
    for (int s = 128; s > 0; s >>= 1) {
        if (tid < s) red[tid] = fmaxf(red[tid], red[tid + s]);
        __syncthreads();
    }
    float rmax = red[0]; __syncthreads();
    float lsum = 0.f;
    for (int j = tid; j < MM_; j += 256) { float e = expf(buf[j] - rmax); buf[j] = e; lsum += e; }
    red[tid] = lsum; __syncthreads();
    for (int s = 128; s > 0; s >>= 1) {
        if (tid < s) red[tid] += red[tid + s];
        __syncthreads();
    }
    float inv = 1.f / red[0];
    for (int j = tid; j < MM_; j += 256) dst[j] = __float2bfloat16(buf[j] * inv);
}

__global__ __launch_bounds__(256)
void softmax_col(const float* __restrict__ sim, bf16* __restrict__ cattn,
                 const void* __restrict__ mask, const void* __restrict__ cmask)
{
    __shared__ float sm[8][32], ss[8][32];
    int mode = g_mask_mode;
    int z = blockIdx.y, b = z / Hh;
    int c = threadIdx.x & 31, g = threadIdx.x >> 5;
    int j = blockIdx.x * 32 + c;
    const float* base = sim   + (long)z * Nn * MM_;
    bf16*        outb = cattn + (long)z * Nn * MM_;
    bool mj = mask_at(cmask, b * MM_ + j, mode);
    float m = -3.402823466e38f, s = 0.f;
    for (int i = g; i < Nn; i += 8) {
        bool mi = mask_at(mask, b * Nn + i, mode);
        float vv = (mj && mi) ? base[(long)i * MM_ + j] : -3.402823466e38f;
        if (vv > m) { s = s * expf(m - vv) + 1.f; m = vv; }
        else        { s += expf(vv - m); }
    }
    sm[g][c] = m; ss[g][c] = s; __syncthreads();
    if (g == 0) {
        float Ml = sm[0][c], Sl = ss[0][c];
        #pragma unroll
        for (int t = 1; t < 8; t++) {
            float mt = sm[t][c], st = ss[t][c];
            float nm = fmaxf(Ml, mt);
            Sl = Sl * expf(Ml - nm) + st * expf(mt - nm);
            Ml = nm;
        }
        sm[0][c] = Ml; ss[0][c] = 1.f / Sl;
    }
    __syncthreads();
    float Mg = sm[0][c], inv = ss[0][c];
    for (int i = g; i < Nn; i += 8) {
        bool mi = mask_at(mask, b * Nn + i, mode);
        float vv = (mj && mi) ? base[(long)i * MM_ + j] : -3.402823466e38f;
        outb[(long)i * MM_ + j] = __float2bfloat16(expf(vv - Mg) * inv);
    }
}

// ---------------- weight transpose + bf16 split -------------------------------
template<bool SPLIT>
__global__ __launch_bounds__(256)
void wt_prep(const float* __restrict__ W, bf16* __restrict__ Th,
             bf16* __restrict__ Tl, int K, int N)
{
    __shared__ float t[32][33];
    int n0 = blockIdx.x * 32, k0 = blockIdx.y * 32;
    int tx = threadIdx.x & 31, ty = threadIdx.x >> 5;
    #pragma unroll
    for (int i = 0; i < 4; i++)
        t[ty + i * 8][tx] = W[(long)(k0 + ty + i * 8) * N + n0 + tx];
    __syncthreads();
    #pragma unroll
    for (int i = 0; i < 4; i++) {
        float v = t[tx][ty + i * 8];
        long o = (long)(n0 + ty + i * 8) * K + k0 + tx;
        bf16 hv = __float2bfloat16(v);
        Th[o] = hv;
        if (SPLIT) Tl[o] = __float2bfloat16(v - __bfloat162float(hv));
    }
}

// ---------------- bf16 WMMA GEMM, 3-stage cp.async ----------------------------
// C = alpha * op(A) @ op(B)  with A [M,K] (or [K,M] if AC), B [K,N] (or [N,K] if BC).
// NT=1: hi operands only. NT=3: Ah*Bh + Ah*Bl + Al*Bh (split bf16, ~16-bit).
// EPI: 0 = f32 direct frag store (alpha); 1 = bf16 hi out;
//      2 = f32 + bias + res;  3 = GELU(v+bias) -> bf16 hi/lo.
__device__ __forceinline__ void cpab(uint32_t s, const void* g)
{ asm volatile("cp.async.cg.shared.global [%0], [%1], 16;\n" :: "r"(s), "l"(g)); }

template<int BM, int BN, bool AC, bool BC, int NT, int EPI>
__global__ __launch_bounds__(256)
void gbf(const bf16* __restrict__ Ah, const bf16* __restrict__ Al, int lda, long aO, long aI,
         const bf16* __restrict__ Bh, const bf16* __restrict__ Bl, int ldb, long bO, long bI,
         float* __restrict__ C, bf16* __restrict__ Cbh, bf16* __restrict__ Cbl,
         int ldc, long cO, long cI,
         const float* __restrict__ bias, const float* __restrict__ res, int ldr,
         int K, float alpha, int HHd)
{
    constexpr int BK   = 32;
    constexpr int LDAS = AC ? BM + 8 : BK + 8;
    constexpr int AEL  = AC ? BK * LDAS : BM * LDAS;
    constexpr int LDBS = BC ? BK + 8 : BN + 8;
    constexpr int BEL  = BC ? BN * LDBS : BK * LDBS;
    constexpr int NM   = (NT == 3) ? 2 : 1;
    constexpr int SEL  = NM * (AEL + BEL);          // elems per stage
    constexpr int WRM  = (BN == 128) ? 2 : 4;
    constexpr int WRN  = 8 / WRM;
    constexpr int TM   = BM / WRM, TN = BN / WRN;
    constexpr int FM   = TM / 16, FN = TN / 16;
    constexpr int oAl  = AEL;
    constexpr int oBh  = NM * AEL;
    constexpr int oBl  = NM * AEL + BEL;

    extern __shared__ bf16 smb_[];
    uint32_t sb0;
    asm("{ .reg .u64 t; cvta.to.shared.u64 t, %1; cvt.u32.u64 %0, t; }"
        : "=r"(sb0) : "l"(smb_));

    int z = blockIdx.z, zo = z / HHd, zi = z % HHd;
    Ah += (long)zo * aO + (long)zi * aI;
    Bh += (long)zo * bO + (long)zi * bI;
    if (NT == 3) { Al += (long)zo * aO + (long)zi * aI; Bl += (long)zo * bO + (long)zi * bI; }
    long m0 = (long)blockIdx.y * BM, n0 = (long)blockIdx.x * BN;
    int tid = threadIdx.x, warp = tid >> 5;
    int wm0 = (warp % WRM) * TM, wn0 = (warp / WRM) * TN;

    auto load_op = [&](uint32_t dst, const bf16* src, int ld, bool tr, int rows, int cols8, long r0, long c0, int kb) {
        // tr=false: [rows][cols8*8] row-major from src[(r0+r)*ld + c0 + kb + c*8]
        int total = rows * cols8;
        for (int idx = tid; idx < total; idx += 256) {
            int r = idx / cols8, c = idx % cols8;
            int LDS_ = tr ? LDAS : (dst >= sb0 + (uint32_t)(oBh * 2) ? LDBS : LDAS);
            (void)LDS_;
            // resolved by caller via precomputed stride
            (void)r; (void)c;
        }
    };
    (void)load_op;

    auto load_stage = [&](int s, int kt) {
        uint32_t base = sb0 + (uint32_t)(s * SEL * 2);
        int kb = kt * BK;
        // A
        if (!AC) {
            constexpr int C8 = BK / 8, TOT = BM * C8;
            for (int idx = tid; idx < TOT; idx += 256) {
                int r = idx / C8, c = idx % C8;
                uint32_t o = base + (uint32_t)((r * LDAS + c * 8) * 2);
                cpab(o, Ah + (m0 + r) * (long)lda + kb + c * 8);
                if (NT == 3) cpab(o + (uint32_t)(oAl * 2), Al + (m0 + r) * (long)lda + kb + c * 8);
            }
        } else {
            constexpr int C8 = BM / 8, TOT = BK * C8;
            for (int idx = tid; idx < TOT; idx += 256) {
                int k = idx / C8, mc = idx % C8;
                uint32_t o = base + (uint32_t)((k * LDAS + mc * 8) * 2);
                cpab(o, Ah + (long)(kb + k) * lda + m0 + mc * 8);
                if (NT == 3) cpab(o + (uint32_t)(oAl * 2), Al + (long)(kb + k) * lda + m0 + mc * 8);
            }
        }
        // B
        if (BC) {
            constexpr int C8 = BK / 8, TOT = BN * C8;
            for (int idx = tid; idx < TOT; idx += 256) {
                int n = idx / C8, c = idx % C8;
                uint32_t o = base + (uint32_t)((oBh + n * LDBS + c * 8) * 2);
                cpab(o, Bh + (n0 + n) * (long)ldb + kb + c * 8);
                if (NT == 3) cpab(o + (uint32_t)((oBl - oBh) * 2), Bl + (n0 + n) * (long)ldb + kb + c * 8);
            }
        } else {
            constexpr int C8 = BN / 8, TOT = BK * C8;
            for (int idx = tid; idx < TOT; idx += 256) {
                int k = idx / C8, c = idx % C8;
                uint32_t o = base + (uint32_t)((oBh + k * LDBS + c * 8) * 2);
                cpab(o, Bh + (long)(kb + k) * ldb + n0 + c * 8);
                if (NT == 3) cpab(o + (uint32_t)((oBl - oBh) * 2), Bl + (long)(kb + k) * ldb + n0 + c * 8);
            }
        }
        asm volatile("cp.async.commit_group;\n");
    };

    using ALay = typename std::conditional<AC, wmma::col_major, wmma::row_major>::type;
    using BLay = typename std::conditional<BC, wmma::col_major, wmma::row_major>::type;
    wmma::fragment<wmma::accumulator, 16, 16, 16, float> fc[FM][FN];
    #pragma unroll
    for (int i = 0; i < FM; i++)
        #pragma unroll
        for (int j = 0; j < FN; j++)
            wmma::fill_fragment(fc[i][j], 0.f);

    int T = K / BK;
    load_stage(0, 0);
    if (T > 1) load_stage(1, 1);

    for (int kt = 0; kt < T; kt++) {
        if (kt + 1 < T) asm volatile("cp.async.wait_group 1;\n");
        else            asm volatile("cp.async.wait_group 0;\n");
        __syncthreads();
        if (kt + 2 < T) load_stage((kt + 2) % 3, kt + 2);

        const bf16* st = smb_ + (kt % 3) * SEL;
        const bf16* sAh = st;
        const bf16* sAl = st + oAl;
        const bf16* sBh = st + oBh;
        const bf16* sBl = st + oBl;

        #pragma unroll
        for (int kk = 0; kk < BK; kk += 16) {
            wmma::fragment<wmma::matrix_a, 16, 16, 16, bf16, ALay> fa[FM], fal[FM];
            wmma::fragment<wmma::matrix_b, 16, 16, 16, bf16, BLay> fb[FN], fbl[FN];
            #pragma unroll
            for (int i = 0; i < FM; i++) {
                const bf16* ap = AC ? (sAh + kk * LDAS + wm0 + i * 16)
                                    : (sAh + (wm0 + i * 16) * LDAS + kk);
                wmma::load_matrix_sync(fa[i], ap, LDAS);
                if (NT == 3) {
                    const bf16* ap2 = AC ? (sAl + kk * LDAS + wm0 + i * 16)
                                         : (sAl + (wm0 + i * 16) * LDAS + kk);
                    wmma::load_matrix_sync(fal[i], ap2, LDAS);
                }
            }
            #pragma unroll
            for (int j = 0; j < FN; j++) {
                const bf16* bp = BC ? (sBh + (wn0 + j * 16) * LDBS + kk)
                                    : (sBh + kk * LDBS + wn0 + j * 16);
                wmma::load_matrix_sync(fb[j], bp, LDBS);
                if (NT == 3) {
                    const bf16* bp2 = BC ? (sBl + (wn0 + j * 16) * LDBS + kk)
                                         : (sBl + kk * LDBS + wn0 + j * 16);
                    wmma::load_matrix_sync(fbl[j], bp2, LDBS);
                }
            }
            #pragma unroll
            for (int i = 0; i < FM; i++)
                #pragma unroll
                for (int j = 0; j < FN; j++) {
                    if (NT == 3) {
                        wmma::mma_sync(fc[i][j], fa[i], fbl[j], fc[i][j]);
                        wmma::mma_sync(fc[i][j], fal[i], fb[j], fc[i][j]);
                    }
                    wmma::mma_sync(fc[i][j], fa[i], fb[j], fc[i][j]);
                }
        }
    }

    if (EPI == 0) {
        #pragma unroll
        for (int i = 0; i < FM; i++)
            #pragma unroll
            for (int j = 0; j < FN; j++) {
                #pragma unroll
                for (int t = 0; t < fc[i][j].num_elements; t++)
                    fc[i][j].x[t] *= alpha;
                wmma::store_matrix_sync(
                    C + (long)zo * cO + (long)zi * cI +
                        (m0 + wm0 + i * 16) * (long)ldc + n0 + wn0 + j * 16,
                    fc[i][j], ldc, wmma::mem_row_major);
            }
        return;
    }

    // staged epilogues (reuse pipeline smem)
    __syncthreads();
    float* sC = (float*)smb_;
    constexpr int LDCS = BN + 4;
    #pragma unroll
    for (int i = 0; i < FM; i++)
        #pragma unroll
        for (int j = 0; j < FN; j++)
            wmma::store_matrix_sync(sC + (wm0 + i * 16) * LDCS + wn0 + j * 16,
                                    fc[i][j], LDCS, wmma::mem_row_major);
    __syncthreads();
    constexpr int NB4 = BN / 4;
    for (int idx = tid; idx < BM * NB4; idx += 256) {
        int r = idx / NB4, c4 = (idx % NB4) * 4;
        long gm = m0 + r, gn = n0 + c4;
        long cb = (long)zo * cO + (long)zi * cI;
        float v0 = sC[r * LDCS + c4 + 0], v1 = sC[r * LDCS + c4 + 1];
        float v2 = sC[r * LDCS + c4 + 2], v3 = sC[r * LDCS + c4 + 3];
        if (EPI == 1) {
            __nv_bfloat162 p0, p1;
            p0.x = __float2bfloat16(v0); p0.y = __float2bfloat16(v1);
            p1.x = __float2bfloat16(v2); p1.y = __float2bfloat16(v3);
            ((__nv_bfloat162*)(Cbh + cb + gm * ldc + gn))[0] = p0;
            ((__nv_bfloat162*)(Cbh + cb + gm * ldc + gn))[1] = p1;
        } else if (EPI == 2) {
            float4 bb = *(const float4*)(bias + gn);
            float4 rr = *(const float4*)(res + gm * (long)ldr + gn);
            float4 o = { v0 + bb.x + rr.x, v1 + bb.y + rr.y,
                         v2 + bb.z + rr.z, v3 + bb.w + rr.w };
            *(float4*)(C + cb + gm * ldc + gn) = o;
        } else {
            float4 bb = *(const float4*)(bias + gn);
            float t0 = v0 + bb.x, t1 = v1 + bb.y, t2 = v2 + bb.z, t3 = v3 + bb.w;
            t0 = 0.5f * t0 * (1.f + erff(t0 * 0.7071067811865476f));
            t1 = 0.5f * t1 * (1.f + erff(t1 * 0.7071067811865476f));
            t2 = 0.5f * t2 * (1.f + erff(t2 * 0.7071067811865476f));
            t3 = 0.5f * t3 * (1.f + erff(t3 * 0.7071067811865476f));
            bf16 h0 = __float2bfloat16(t0), h1 = __float2bfloat16(t1);
            bf16 h2 = __float2bfloat16(t2), h3 = __float2bfloat16(t3);
            __nv_bfloat162 hp0, hp1, lp0, lp1;
            hp0.x = h0; hp0.y = h1; hp1.x = h2; hp1.y = h3;
            lp0.x = __float2bfloat16(t0 - __bfloat162float(h0));
            lp0.y = __float2bfloat16(t1 - __bfloat162float(h1));
            lp1.x = __float2bfloat16(t2 - __bfloat162float(h2));
            lp1.y = __float2bfloat16(t3 - __bfloat162float(h3));
            ((__nv_bfloat162*)(Cbh + gm * ldc + gn))[0] = hp0;
            ((__nv_bfloat162*)(Cbh + gm * ldc + gn))[1] = hp1;
            ((__nv_bfloat162*)(Cbl + gm * ldc + gn))[0] = lp0;
            ((__nv_bfloat162*)(Cbl + gm * ldc + gn))[1] = lp1;
        }
    }
}

static constexpr size_t gsm(int BM, int BN, bool AC, bool BC, int NT)
{
    int LDAS = AC ? BM + 8 : 40;
    int AEL  = AC ? 32 * LDAS : BM * LDAS;
    int LDBS = BC ? 40 : BN + 8;
    int BEL  = BC ? BN * LDBS : 32 * LDBS;
    int NM   = (NT == 3) ? 2 : 1;
    size_t pipe = 3u * 2u * (size_t)(NM * (AEL + BEL));
    size_t epi  = 4u * (size_t)BM * (BN + 4);
    return pipe > epi ? pipe : epi;
}

#define LGB(BM, BN, AC, BC, NT, EPI, grid, ...)                                  \
    do {                                                                         \
        auto kfn = gbf<BM, BN, AC, BC, NT, EPI>;                                 \
        size_t smb = gsm(BM, BN, AC, BC, NT);                                    \
        cudaFuncSetAttribute(kfn, cudaFuncAttributeMaxDynamicSharedMemorySize, (int)smb); \
        kfn<<<grid, 256, smb>>>(__VA_ARGS__);                                    \
    } while (0)

// ---------------- host ----------------------------------------------------------
extern "C" void kernel_launch(void* const* d_in, const int* in_sizes, int n_in,
                              void* d_out, int out_size)
{
    (void)in_sizes; (void)n_in; (void)out_size;
    const float* x      = (const float*)d_in[0];
    const float* ctx    = (const float*)d_in[1];
    const void*  mask   = d_in[2];
    const void*  cmask  = d_in[3];
    const float* ln_x_g = (const float*)d_in[4];
    const float* ln_x_b = (const float*)d_in[5];
    const float* ln_c_g = (const float*)d_in[6];
    const float* ln_c_b = (const float*)d_in[7];
    const float* W_qk   = (const float*)d_in[8];
    const float* W_v    = (const float*)d_in[9];
    const float* Wc_qk  = (const float*)d_in[10];
    const float* Wc_v   = (const float*)d_in[11];
    const float* W_out  = (const float*)d_in[12];
    const float* b_out  = (const float*)d_in[13];
    const float* Wc_out = (const float*)d_in[14];
    const float* bc_out = (const float*)d_in[15];
    const float* ff_g   = (const float*)d_in[16];
    const float* ff_b   = (const float*)d_in[17];
    const float* ff_w1  = (const float*)d_in[18];
    const float* ff_b1  = (const float*)d_in[19];
    const float* ff_w2  = (const float*)d_in[20];
    const float* ff_b2  = (const float*)d_in[21];
    const float* cff_g  = (const float*)d_in[22];
    const float* cff_b  = (const float*)d_in[23];
    const float* cff_w1 = (const float*)d_in[24];
    const float* cff_b1 = (const float*)d_in[25];
    const float* cff_w2 = (const float*)d_in[26];
    const float* cff_b2 = (const float*)d_in[27];
    float* outp = (float*)d_out;

    float *sim, *x1, *c1;
    bf16 *attn, *cattn, *qk, *v, *cqk, *cv, *out, *cout;
    bf16 *xnh, *xnl, *cnh, *cnl, *hh, *hl, *wph, *woh, *f1h, *f1l, *f2h, *f2l;
    cudaGetSymbolAddress((void**)&sim,   g_sim);
    cudaGetSymbolAddress((void**)&x1,    g_x1);
    cudaGetSymbolAddress((void**)&c1,    g_c1);
    cudaGetSymbolAddress((void**)&attn,  g_attn);
    cudaGetSymbolAddress((void**)&cattn, g_cattn);
    cudaGetSymbolAddress((void**)&qk,    g_qk);
    cudaGetSymbolAddress((void**)&v,     g_v);
    cudaGetSymbolAddress((void**)&cqk,   g_cqk);
    cudaGetSymbolAddress((void**)&cv,    g_cv);
    cudaGetSymbolAddress((void**)&out,   g_out);
    cudaGetSymbolAddress((void**)&cout,  g_cout);
    cudaGetSymbolAddress((void**)&xnh,   g_xnh);
    cudaGetSymbolAddress((void**)&xnl,   g_xnl);
    cudaGetSymbolAddress((void**)&cnh,   g_cnh);
    cudaGetSymbolAddress((void**)&cnl,   g_cnl);
    cudaGetSymbolAddress((void**)&hh,    g_hh);
    cudaGetSymbolAddress((void**)&hl,    g_hl);
    cudaGetSymbolAddress((void**)&wph,   g_wph);
    cudaGetSymbolAddress((void**)&woh,   g_woh);
    cudaGetSymbolAddress((void**)&f1h,   g_f1h);
    cudaGetSymbolAddress((void**)&f1l,   g_f1l);
    cudaGetSymbolAddress((void**)&f2h,   g_f2h);
    cudaGetSymbolAddress((void**)&f2l,   g_f2l);

    const float SCALE = 0.125f;
    const long PW = (long)INNERi * Dd;
    const long FW = (long)FFDf * Dd;
    const bf16* nb = nullptr;
    bf16* nbm = nullptr;
    const float* nf = nullptr;

    detect_mask_mode<<<1, 256>>>((const float*)mask, (Bb * Nn) / 4);
    wt_prep<false><<<dim3(INNERi / 32, Dd / 32), 256>>>(W_qk,  wph + 0 * PW, nullptr, Dd, INNERi);
    wt_prep<false><<<dim3(INNERi / 32, Dd / 32), 256>>>(W_v,   wph + 1 * PW, nullptr, Dd, INNERi);
    wt_prep<false><<<dim3(INNERi / 32, Dd / 32), 256>>>(Wc_qk, wph + 2 * PW, nullptr, Dd, INNERi);
    wt_prep<false><<<dim3(INNERi / 32, Dd / 32), 256>>>(Wc_v,  wph + 3 * PW, nullptr, Dd, INNERi);
    wt_prep<false><<<dim3(Dd / 32, INNERi / 32), 256>>>(W_out,  woh + 0 * PW, nullptr, INNERi, Dd);
    wt_prep<false><<<dim3(Dd / 32, INNERi / 32), 256>>>(Wc_out, woh + 1 * PW, nullptr, INNERi, Dd);
    wt_prep<true><<<dim3(FFDf / 32, Dd / 32), 256>>>(ff_w1,  f1h + 0 * FW, f1l + 0 * FW, Dd, FFDf);
    wt_prep<true><<<dim3(FFDf / 32, Dd / 32), 256>>>(cff_w1, f1h + 1 * FW, f1l + 1 * FW, Dd, FFDf);
    wt_prep<true><<<dim3(Dd / 32, FFDf / 32), 256>>>(ff_w2,  f2h + 0 * FW, f2l + 0 * FW, FFDf, Dd);
    wt_prep<true><<<dim3(Dd / 32, FFDf / 32), 256>>>(cff_w2, f2h + 1 * FW, f2l + 1 * FW, FFDf, Dd);

    ln_bf<<<Bb * Nn,  256>>>(x,   ln_x_g, ln_x_b, xnh, xnl, Dd);
    ln_bf<<<Bb * MM_, 256>>>(ctx, ln_c_g, ln_c_b, cnh, cnl, Dd);

    // projections: bf16 in/out, W [N,K] col-frag
    LGB(64, 128, false, true, 1, 1, dim3(INNERi / 128, Bb * Nn / 64, 1),
        xnh, nb, Dd, 0, 0, wph + 0 * PW, nb, Dd, 0, 0,
        (float*)nullptr, qk, nbm, INNERi, 0, 0, nf, nf, 0, Dd, 1.f, 1);
    LGB(64, 128, false, true, 1, 1, dim3(INNERi / 128, Bb * Nn / 64, 1),
        xnh, nb, Dd, 0, 0, wph + 1 * PW, nb, Dd, 0, 0,
        (float*)nullptr, v, nbm, INNERi, 0, 0, nf, nf, 0, Dd, 1.f, 1);
    LGB(64, 128, false, true, 1, 1, dim3(INNERi / 128, Bb * MM_ / 64, 1),
        cnh, nb, Dd, 0, 0, wph + 2 * PW, nb, Dd, 0, 0,
        (float*)nullptr, cqk, nbm, INNERi, 0, 0, nf, nf, 0, Dd, 1.f, 1);
    LGB(64, 128, false, true, 1, 1, dim3(INNERi / 128, Bb * MM_ / 64, 1),
        cnh, nb, Dd, 0, 0, wph + 3 * PW, nb, Dd, 0, 0,
        (float*)nullptr, cv, nbm, INNERi, 0, 0, nf, nf, 0, Dd, 1.f, 1);

    // sim = qk @ cqk^T * SCALE (f32 out, batched b*h)
    LGB(64, 128, false, true, 1, 0, dim3(MM_ / 128, Nn / 64, Bb * Hh),
        qk, nb, INNERi, (long)Nn * INNERi, DHd,
        cqk, nb, INNERi, (long)MM_ * INNERi, DHd,
        sim, nbm, nbm, MM_, (long)Hh * Nn * MM_, (long)Nn * MM_,
        nf, nf, 0, DHd, SCALE, Hh);

    softmax_row<<<Bb * Hh * Nn, 256>>>(sim, attn, mask, cmask);
    softmax_col<<<dim3(MM_ / 32, Bb * Hh), 256>>>(sim, cattn, mask, cmask);

    // PV: out = attn @ cv ; cout = cattn^T @ v (bf16 out)
    LGB(64, 64, false, false, 1, 1, dim3(1, Nn / 64, Bb * Hh),
        attn, nb, MM_, (long)Hh * Nn * MM_, (long)Nn * MM_,
        cv, nb, INNERi, (long)MM_ * INNERi, DHd,
        (float*)nullptr, out, nbm, INNERi, (long)Nn * INNERi, DHd,
        nf, nf, 0, MM_, 1.f, Hh);
    LGB(64, 64, true, false, 1, 1, dim3(1, MM_ / 64, Bb * Hh),
        cattn, nb, MM_, (long)Hh * Nn * MM_, (long)Nn * MM_,
        v, nb, INNERi, (long)Nn * INNERi, DHd,
        (float*)nullptr, cout, nbm, INNERi, (long)MM_ * INNERi, DHd,
        nf, nf, 0, Nn, 1.f, Hh);

    // out-proj + residual (f32)
    LGB(64, 128, false, true, 1, 2, dim3(Dd / 128, Bb * Nn / 64, 1),
        out, nb, INNERi, 0, 0, woh + 0 * PW, nb, INNERi, 0, 0,
        x1, nbm, nbm, Dd, 0, 0, b_out, x, Dd, INNERi, 1.f, 1);
    LGB(64, 128, false, true, 1, 2, dim3(Dd / 128, Bb * MM_ / 64, 1),
        cout, nb, INNERi, 0, 0, woh + 1 * PW, nb, INNERi, 0, 0,
        c1, nbm, nbm, Dd, 0, 0, bc_out, ctx, Dd, INNERi, 1.f, 1);

    // FFN x-side (3-term split bf16)
    ln_bf<<<Bb * Nn, 256>>>(x1, ff_g, ff_b, xnh, xnl, Dd);
    LGB(64, 128, false, true, 3, 3, dim3(FFDf / 128, Bb * Nn / 64, 1),
        xnh, xnl, Dd, 0, 0, f1h + 0 * FW, f1l + 0 * FW, Dd, 0, 0,
        (float*)nullptr, hh, hl, FFDf, 0, 0, ff_b1, nf, 0, Dd, 1.f, 1);
    LGB(64, 128, false, true, 3, 2, dim3(Dd / 128, Bb * Nn / 64, 1),
        hh, hl, FFDf, 0, 0, f2h + 0 * FW, f2l + 0 * FW, FFDf, 0, 0,
        outp, nbm, nbm, Dd, 0, 0, ff_b2, x1, Dd, FFDf, 1.f, 1);

    // FFN context-side
    ln_bf<<<Bb * MM_, 256>>>(c1, cff_g, cff_b, cnh, cnl, Dd);
    LGB(64, 128, false, true, 3, 3, dim3(FFDf / 128, Bb * MM_ / 64, 1),
        cnh, cnl, Dd, 0, 0, f1h + 1 * FW, f1l + 1 * FW, Dd, 0, 0,
        (float*)nullptr, hh, hl, FFDf, 0, 0, cff_b1, nf, 0, Dd, 1.f, 1);
    LGB(64, 128, false, true, 3, 2, dim3(Dd / 128, Bb * MM_ / 64, 1),
        hh, hl, FFDf, 0, 0, f2h + 1 * FW, f2l + 1 * FW, FFDf, 0, 0,
        outp + (long)Bb * Nn * Dd, nbm, nbm, Dd, 0, 0, cff_b2, c1, Dd, FFDf, 1.f, 1);
}

// round 10
// speedup vs baseline: 1.3772x; 1.0327x over previous
#include <cuda_runtime.h>
#include <cuda_bf16.h>
#include <mma.h>
#include <math.h>
#include <cstdint>

using namespace nvcuda;
typedef __nv_bfloat16 bf16;

#define Bb 2
#define Nn 2048
#define MM_ 2048
#define Dd 1024
#define Hh 8
#define DHd 64
#define INNERi 512
#define FFDf 4096

// ---------------- scratch ----------------------------------------------------
__device__ __align__(256) float g_sim  [Bb*Hh*Nn*MM_];
__device__ __align__(256) float g_x1  [Bb*Nn*Dd];
__device__ __align__(256) float g_c1  [Bb*MM_*Dd];
__device__ __align__(256) bf16 g_attn [Bb*Hh*Nn*MM_];
__device__ __align__(256) bf16 g_cattn[Bb*Hh*Nn*MM_];
__device__ __align__(256) bf16 g_qk [Bb*Nn*INNERi];
__device__ __align__(256) bf16 g_v  [Bb*Nn*INNERi];
__device__ __align__(256) bf16 g_cqk[Bb*MM_*INNERi];
__device__ __align__(256) bf16 g_cv [Bb*MM_*INNERi];
__device__ __align__(256) bf16 g_out [Bb*Nn*INNERi];
__device__ __align__(256) bf16 g_cout[Bb*MM_*INNERi];
__device__ __align__(256) bf16 g_xnh[Bb*Nn*Dd];
__device__ __align__(256) bf16 g_xnl[Bb*Nn*Dd];
__device__ __align__(256) bf16 g_cnh[Bb*MM_*Dd];
__device__ __align__(256) bf16 g_cnl[Bb*MM_*Dd];
__device__ __align__(256) bf16 g_hh[Bb*Nn*FFDf];
__device__ __align__(256) bf16 g_hl[Bb*Nn*FFDf];
__device__ __align__(256) bf16 g_wph[4*INNERi*Dd];
__device__ __align__(256) bf16 g_woh[2*Dd*INNERi];
__device__ __align__(256) bf16 g_f1h[2*FFDf*Dd];
__device__ __align__(256) bf16 g_f1l[2*FFDf*Dd];
__device__ __align__(256) bf16 g_f2h[2*Dd*FFDf];
__device__ __align__(256) bf16 g_f2l[2*Dd*FFDf];
__device__ int g_mask_mode;

// ---------------- mask detection ---------------------------------------------
__global__ void detect_mask_mode(const float* __restrict__ fp, int n4)
{
    __shared__ int okf_s, oki_s;
    if (threadIdx.x == 0) { okf_s = 1; oki_s = 1; }
    __syncthreads();
    const int* ip = (const int*)fp;
    bool okf = true, oki = true;
    for (int i = threadIdx.x; i < n4; i += 256) {
        float fv = fp[i]; okf = okf && (fv == 0.f || fv == 1.f);
        int   iv = ip[i]; oki = oki && (iv == 0 || iv == 1);
    }
    if (!okf) atomicAnd(&okf_s, 0);
    if (!oki) atomicAnd(&oki_s, 0);
    __syncthreads();
    if (threadIdx.x == 0) g_mask_mode = okf_s ? 2 : (oki_s ? 1 : 0);
}
__device__ __forceinline__ bool mask_at(const void* m, int i, int mode)
{
    if (mode == 1) return ((const int*)m)[i] != 0;
    if (mode == 2) return ((const float*)m)[i] != 0.f;
    return ((const unsigned char*)m)[i] != 0;
}

// ---------------- LayerNorm -> bf16 hi/lo ------------------------------------
__global__ __launch_bounds__(256)
void ln_bf(const float* __restrict__ in, const float* __restrict__ g,
           const float* __restrict__ b, bf16* __restrict__ oh,
           bf16* __restrict__ ol, int cols)
{
    __shared__ float r1[256], r2[256];
    long row = blockIdx.x;
    const float* p = in + row * cols;
    bf16* ph = oh + row * cols;
    bf16* pl = ol + row * cols;
    int tid = threadIdx.x;
    float s = 0.f, s2 = 0.f;
    for (int c = tid; c < cols; c += 256) { float v = p[c]; s += v; s2 += v * v; }
    r1[tid] = s; r2[tid] = s2; __syncthreads();
    for (int st = 128; st > 0; st >>= 1) {
        if (tid < st) { r1[tid] += r1[tid + st]; r2[tid] += r2[tid + st]; }
        __syncthreads();
    }
    float mu  = r1[0] / cols;
    float var = r2[0] / cols - mu * mu;
    float inv = rsqrtf(var + 1e-5f);
    for (int c = tid; c < cols; c += 256) {
        float y = (p[c] - mu) * inv * g[c] + b[c];
        bf16 hv = __float2bfloat16(y);
        ph[c] = hv;
        pl[c] = __float2bfloat16(y - __bfloat162float(hv));
    }
}

// ---------------- dual softmax (bf16 outputs) ---------------------------------
__global__ __launch_bounds__(256)
void softmax_row(const float* __restrict__ sim, bf16* __restrict__ attn,
                 const void* __restrict__ mask, const void* __restrict__ cmask)
{
    __shared__ float buf[MM_];
    __shared__ float red[256];
    int mode = g_mask_mode;
    long row = blockIdx.x;
    int i = (int)(row % Nn), bh = (int)(row / Nn), b = bh / Hh;
    const float* src = sim  + row * (long)MM_;
    bf16*        dst = attn + row * (long)MM_;
    int tid = threadIdx.x;
    bool mi = mask_at(mask, b * Nn + i, mode);
    float lmax = -3.402823466e38f;
    for (int j = tid; j < MM_; j += 256) {
        bool mj = mask_at(cmask, b * MM_ + j, mode);
        float vv = (mi && mj) ? src[j] : -3.402823466e38f;
        buf[j] = vv; lmax = fmaxf(lmax, vv);
    }
    red[tid] = lmax; __syncthreads();
    for (int s = 128; s > 0; s >>= 1) {
        if (tid < s) red[tid] = fmaxf(red[tid], red[tid + s]);
        __syncthreads();
    }
    float rmax = red[0]; __syncthreads();
    float lsum = 0.f;
    for (int j = tid; j < MM_; j += 256) { float e = expf(buf[j] - rmax); buf[j] = e; lsum += e; }
    red[tid] = lsum; __syncthreads();
    for (int s = 128; s > 0; s >>= 1) {
        if (tid < s) red[tid] += red[tid + s];
        __syncthreads();
    }
    float inv = 1.f / red[0];
    for (int j = tid; j < MM_; j += 256) dst[j] = __float2bfloat16(buf[j] * inv);
}

__global__ __launch_bounds__(256)
void softmax_col(const float* __restrict__ sim, bf16* __restrict__ cattn,
                 const void* __restrict__ mask, const void* __restrict__ cmask)
{
    __shared__ float sm[8][32], ss[8][32];
    int mode = g_mask_mode;
    int z = blockIdx.y, b = z / Hh;
    int c = threadIdx.x & 31, g = threadIdx.x >> 5;
    int j = blockIdx.x * 32 + c;
    const float* base = sim   + (long)z * Nn * MM_;
    bf16*        outb = cattn + (long)z * Nn * MM_;
    bool mj = mask_at(cmask, b * MM_ + j, mode);
    float m = -3.402823466e38f, s = 0.f;
    for (int i = g; i < Nn; i += 8) {
        bool mi = mask_at(mask, b * Nn + i, mode);
        float vv = (mj && mi) ? base[(long)i * MM_ + j] : -3.402823466e38f;
        if (vv > m) { s = s * expf(m - vv) + 1.f; m = vv; }
        else        { s += expf(vv - m); }
    }
    sm[g][c] = m; ss[g][c] = s; __syncthreads();
    if (g == 0) {
        float Ml = sm[0][c], Sl = ss[0][c];
        #pragma unroll
        for (int t = 1; t < 8; t++) {
            float mt = sm[t][c], st = ss[t][c];
            float nm = fmaxf(Ml, mt);
            Sl = Sl * expf(Ml - nm) + st * expf(mt - nm);
            Ml = nm;
        }
        sm[0][c] = Ml; ss[0][c] = 1.f / Sl;
    }
    __syncthreads();
    float Mg = sm[0][c], inv = ss[0][c];
    for (int i = g; i < Nn; i += 8) {
        bool mi = mask_at(mask, b * Nn + i, mode);
        float vv = (mj && mi) ? base[(long)i * MM_ + j] : -3.402823466e38f;
        outb[(long)i * MM_ + j] = __float2bfloat16(expf(vv - Mg) * inv);
    }
}

// ---------------- weight transpose + bf16 split -------------------------------
template<bool SPLIT>
__global__ __launch_bounds__(256)
void wt_prep(const float* __restrict__ W, bf16* __restrict__ Th,
             bf16* __restrict__ Tl, int K, int N)
{
    __shared__ float t[32][33];
    int n0 = blockIdx.x * 32, k0 = blockIdx.y * 32;
    int tx = threadIdx.x & 31, ty = threadIdx.x >> 5;
    #pragma unroll
    for (int i = 0; i < 4; i++)
        t[ty + i * 8][tx] = W[(long)(k0 + ty + i * 8) * N + n0 + tx];
    __syncthreads();
    #pragma unroll
    for (int i = 0; i < 4; i++) {
        float v = t[tx][ty + i * 8];
        long o = (long)(n0 + ty + i * 8) * K + k0 + tx;
        bf16 hv = __float2bfloat16(v);
        Th[o] = hv;
        if (SPLIT) Tl[o] = __float2bfloat16(v - __bfloat162float(hv));
    }
}

// ---------------- bf16 WMMA GEMM, 3-stage cp.async ----------------------------
// C = alpha * op(A) @ op(B)  with A [M,K] (or [K,M] if AC), B [K,N] (or [N,K] if BC).
// NT=1: hi operands only. NT=3: Ah*Bh + Ah*Bl + Al*Bh (split bf16, ~16-bit).
// EPI: 0 = f32 direct frag store (alpha); 1 = bf16 hi out;
//      2 = f32 + bias + res;  3 = GELU(v+bias) -> bf16 hi/lo.
__device__ __forceinline__ void cpab(uint32_t s, const void* g)
{ asm volatile("cp.async.cg.shared.global [%0], [%1], 16;\n" :: "r"(s), "l"(g)); }

template<int BM, int BN, bool AC, bool BC, int NT, int EPI>
__global__ __launch_bounds__(256)
void gbf(const bf16* __restrict__ Ah, const bf16* __restrict__ Al, int lda, long aO, long aI,
         const bf16* __restrict__ Bh, const bf16* __restrict__ Bl, int ldb, long bO, long bI,
         float* __restrict__ C, bf16* __restrict__ Cbh, bf16* __restrict__ Cbl,
         int ldc, long cO, long cI,
         const float* __restrict__ bias, const float* __restrict__ res, int ldr,
         int K, float alpha, int HHd)
{
    constexpr int BK   = 32;
    constexpr int LDAS = AC ? BM + 8 : BK + 8;
    constexpr int AEL  = AC ? BK * LDAS : BM * LDAS;
    constexpr int LDBS = BC ? BK + 8 : BN + 8;
    constexpr int BEL  = BC ? BN * LDBS : BK * LDBS;
    constexpr int NM   = (NT == 3) ? 2 : 1;
    constexpr int SEL  = NM * (AEL + BEL);
    constexpr int WRM  = (BN == 128) ? 2 : 4;
    constexpr int WRN  = 8 / WRM;
    constexpr int TM   = BM / WRM, TN = BN / WRN;
    constexpr int FM   = TM / 16, FN = TN / 16;
    constexpr int oAl  = AEL;
    constexpr int oBh  = NM * AEL;
    constexpr int oBl  = NM * AEL + BEL;

    extern __shared__ bf16 smb_[];
    uint32_t sb0;
    asm("{ .reg .u64 t; cvta.to.shared.u64 t, %1; cvt.u32.u64 %0, t; }"
        : "=r"(sb0) : "l"(smb_));

    int z = blockIdx.z, zo = z / HHd, zi = z % HHd;
    Ah += (long)zo * aO + (long)zi * aI;
    Bh += (long)zo * bO + (long)zi * bI;
    if (NT == 3) { Al += (long)zo * aO + (long)zi * aI; Bl += (long)zo * bO + (long)zi * bI; }
    long m0 = (long)blockIdx.y * BM, n0 = (long)blockIdx.x * BN;
    int tid = threadIdx.x, warp = tid >> 5;
    int wm0 = (warp % WRM) * TM, wn0 = (warp / WRM) * TN;

    auto load_stage = [&](int s, int kt) {
        uint32_t base = sb0 + (uint32_t)(s * SEL * 2);
        int kb = kt * BK;
        if (!AC) {
            constexpr int C8 = BK / 8, TOT = BM * C8;
            for (int idx = tid; idx < TOT; idx += 256) {
                int r = idx / C8, c = idx % C8;
                uint32_t o = base + (uint32_t)((r * LDAS + c * 8) * 2);
                cpab(o, Ah + (m0 + r) * (long)lda + kb + c * 8);
                if (NT == 3) cpab(o + (uint32_t)(oAl * 2), Al + (m0 + r) * (long)lda + kb + c * 8);
            }
        } else {
            constexpr int C8 = BM / 8, TOT = BK * C8;
            for (int idx = tid; idx < TOT; idx += 256) {
                int k = idx / C8, mc = idx % C8;
                uint32_t o = base + (uint32_t)((k * LDAS + mc * 8) * 2);
                cpab(o, Ah + (long)(kb + k) * lda + m0 + mc * 8);
                if (NT == 3) cpab(o + (uint32_t)(oAl * 2), Al + (long)(kb + k) * lda + m0 + mc * 8);
            }
        }
        if (BC) {
            constexpr int C8 = BK / 8, TOT = BN * C8;
            for (int idx = tid; idx < TOT; idx += 256) {
                int n = idx / C8, c = idx % C8;
                uint32_t o = base + (uint32_t)((oBh + n * LDBS + c * 8) * 2);
                cpab(o, Bh + (n0 + n) * (long)ldb + kb + c * 8);
                if (NT == 3) cpab(o + (uint32_t)((oBl - oBh) * 2), Bl + (n0 + n) * (long)ldb + kb + c * 8);
            }
        } else {
            constexpr int C8 = BN / 8, TOT = BK * C8;
            for (int idx = tid; idx < TOT; idx += 256) {
                int k = idx / C8, c = idx % C8;
                uint32_t o = base + (uint32_t)((oBh + k * LDBS + c * 8) * 2);
                cpab(o, Bh + (long)(kb + k) * ldb + n0 + c * 8);
                if (NT == 3) cpab(o + (uint32_t)((oBl - oBh) * 2), Bl + (long)(kb + k) * ldb + n0 + c * 8);
            }
        }
        asm volatile("cp.async.commit_group;\n");
    };

    using ALay = typename std::conditional<AC, wmma::col_major, wmma::row_major>::type;
    using BLay = typename std::conditional<BC, wmma::col_major, wmma::row_major>::type;
    wmma::fragment<wmma::accumulator, 16, 16, 16, float> fc[FM][FN];
    #pragma unroll
    for (int i = 0; i < FM; i++)
        #pragma unroll
        for (int j = 0; j < FN; j++)
            wmma::fill_fragment(fc[i][j], 0.f);

    int T = K / BK;
    load_stage(0, 0);
    if (T > 1) load_stage(1, 1);

    for (int kt = 0; kt < T; kt++) {
        if (kt + 1 < T) asm volatile("cp.async.wait_group 1;\n");
        else            asm volatile("cp.async.wait_group 0;\n");
        __syncthreads();
        if (kt + 2 < T) load_stage((kt + 2) % 3, kt + 2);

        const bf16* st = smb_ + (kt % 3) * SEL;
        const bf16* sAh = st;
        const bf16* sAl = st + oAl;
        const bf16* sBh = st + oBh;
        const bf16* sBl = st + oBl;

        #pragma unroll
        for (int kk = 0; kk < BK; kk += 16) {
            wmma::fragment<wmma::matrix_a, 16, 16, 16, bf16, ALay> fa[FM], fal[FM];
            wmma::fragment<wmma::matrix_b, 16, 16, 16, bf16, BLay> fb[FN], fbl[FN];
            #pragma unroll
            for (int i = 0; i < FM; i++) {
                const bf16* ap = AC ? (sAh + kk * LDAS + wm0 + i * 16)
                                    : (sAh + (wm0 + i * 16) * LDAS + kk);
                wmma::load_matrix_sync(fa[i], ap, LDAS);
                if (NT == 3) {
                    const bf16* ap2 = AC ? (sAl + kk * LDAS + wm0 + i * 16)
                                         : (sAl + (wm0 + i * 16) * LDAS + kk);
                    wmma::load_matrix_sync(fal[i], ap2, LDAS);
                }
            }
            #pragma unroll
            for (int j = 0; j < FN; j++) {
                const bf16* bp = BC ? (sBh + (wn0 + j * 16) * LDBS + kk)
                                    : (sBh + kk * LDBS + wn0 + j * 16);
                wmma::load_matrix_sync(fb[j], bp, LDBS);
                if (NT == 3) {
                    const bf16* bp2 = BC ? (sBl + (wn0 + j * 16) * LDBS + kk)
                                         : (sBl + kk * LDBS + wn0 + j * 16);
                    wmma::load_matrix_sync(fbl[j], bp2, LDBS);
                }
            }
            #pragma unroll
            for (int i = 0; i < FM; i++)
                #pragma unroll
                for (int j = 0; j < FN; j++) {
                    if (NT == 3) {
                        wmma::mma_sync(fc[i][j], fa[i], fbl[j], fc[i][j]);
                        wmma::mma_sync(fc[i][j], fal[i], fb[j], fc[i][j]);
                    }
                    wmma::mma_sync(fc[i][j], fa[i], fb[j], fc[i][j]);
                }
        }
    }

    if (EPI == 0) {
        #pragma unroll
        for (int i = 0; i < FM; i++)
            #pragma unroll
            for (int j = 0; j < FN; j++) {
                #pragma unroll
                for (int t = 0; t < fc[i][j].num_elements; t++)
                    fc[i][j].x[t] *= alpha;
                wmma::store_matrix_sync(
                    C + (long)zo * cO + (long)zi * cI +
                        (m0 + wm0 + i * 16) * (long)ldc + n0 + wn0 + j * 16,
                    fc[i][j], ldc, wmma::mem_row_major);
            }
        return;
    }

    __syncthreads();
    float* sC = (float*)smb_;
    constexpr int LDCS = BN + 4;
    #pragma unroll
    for (int i = 0; i < FM; i++)
        #pragma unroll
        for (int j = 0; j < FN; j++)
            wmma::store_matrix_sync(sC + (wm0 + i * 16) * LDCS + wn0 + j * 16,
                                    fc[i][j], LDCS, wmma::mem_row_major);
    __syncthreads();
    constexpr int NB4 = BN / 4;
    for (int idx = tid; idx < BM * NB4; idx += 256) {
        int r = idx / NB4, c4 = (idx % NB4) * 4;
        long gm = m0 + r, gn = n0 + c4;
        long cb = (long)zo * cO + (long)zi * cI;
        float v0 = sC[r * LDCS + c4 + 0], v1 = sC[r * LDCS + c4 + 1];
        float v2 = sC[r * LDCS + c4 + 2], v3 = sC[r * LDCS + c4 + 3];
        if (EPI == 1) {
            __nv_bfloat162 p0, p1;
            p0.x = __float2bfloat16(v0); p0.y = __float2bfloat16(v1);
            p1.x = __float2bfloat16(v2); p1.y = __float2bfloat16(v3);
            ((__nv_bfloat162*)(Cbh + cb + gm * ldc + gn))[0] = p0;
            ((__nv_bfloat162*)(Cbh + cb + gm * ldc + gn))[1] = p1;
        } else if (EPI == 2) {
            float4 bb = *(const float4*)(bias + gn);
            float4 rr = *(const float4*)(res + gm * (long)ldr + gn);
            float4 o = { v0 + bb.x + rr.x, v1 + bb.y + rr.y,
                         v2 + bb.z + rr.z, v3 + bb.w + rr.w };
            *(float4*)(C + cb + gm * ldc + gn) = o;
        } else {
            float4 bb = *(const float4*)(bias + gn);
            float t0 = v0 + bb.x, t1 = v1 + bb.y, t2 = v2 + bb.z, t3 = v3 + bb.w;
            t0 = 0.5f * t0 * (1.f + erff(t0 * 0.7071067811865476f));
            t1 = 0.5f * t1 * (1.f + erff(t1 * 0.7071067811865476f));
            t2 = 0.5f * t2 * (1.f + erff(t2 * 0.7071067811865476f));
            t3 = 0.5f * t3 * (1.f + erff(t3 * 0.7071067811865476f));
            bf16 h0 = __float2bfloat16(t0), h1 = __float2bfloat16(t1);
            bf16 h2 = __float2bfloat16(t2), h3 = __float2bfloat16(t3);
            __nv_bfloat162 hp0, hp1, lp0, lp1;
            hp0.x = h0; hp0.y = h1; hp1.x = h2; hp1.y = h3;
            lp0.x = __float2bfloat16(t0 - __bfloat162float(h0));
            lp0.y = __float2bfloat16(t1 - __bfloat162float(h1));
            lp1.x = __float2bfloat16(t2 - __bfloat162float(h2));
            lp1.y = __float2bfloat16(t3 - __bfloat162float(h3));
            ((__nv_bfloat162*)(Cbh + gm * ldc + gn))[0] = hp0;
            ((__nv_bfloat162*)(Cbh + gm * ldc + gn))[1] = hp1;
            ((__nv_bfloat162*)(Cbl + gm * ldc + gn))[0] = lp0;
            ((__nv_bfloat162*)(Cbl + gm * ldc + gn))[1] = lp1;
        }
    }
}

static constexpr size_t gsm(int BM, int BN, bool AC, bool BC, int NT)
{
    int LDAS = AC ? BM + 8 : 40;
    int AEL  = AC ? 32 * LDAS : BM * LDAS;
    int LDBS = BC ? 40 : BN + 8;
    int BEL  = BC ? BN * LDBS : 32 * LDBS;
    int NM   = (NT == 3) ? 2 : 1;
    size_t pipe = 3u * 2u * (size_t)(NM * (AEL + BEL));
    size_t epi  = 4u * (size_t)BM * (BN + 4);
    return pipe > epi ? pipe : epi;
}

#define LGB(BM, BN, AC, BC, NT, EPI, grid, ...)                                  \
    do {                                                                         \
        auto kfn = gbf<BM, BN, AC, BC, NT, EPI>;                                 \
        size_t smb = gsm(BM, BN, AC, BC, NT);                                    \
        cudaFuncSetAttribute(kfn, cudaFuncAttributeMaxDynamicSharedMemorySize, (int)smb); \
        kfn<<<grid, 256, smb>>>(__VA_ARGS__);                                    \
    } while (0)

// ---------------- host ----------------------------------------------------------
extern "C" void kernel_launch(void* const* d_in, const int* in_sizes, int n_in,
                              void* d_out, int out_size)
{
    (void)in_sizes; (void)n_in; (void)out_size;
    const float* x      = (const float*)d_in[0];
    const float* ctx    = (const float*)d_in[1];
    const void*  mask   = d_in[2];
    const void*  cmask  = d_in[3];
    const float* ln_x_g = (const float*)d_in[4];
    const float* ln_x_b = (const float*)d_in[5];
    const float* ln_c_g = (const float*)d_in[6];
    const float* ln_c_b = (const float*)d_in[7];
    const float* W_qk   = (const float*)d_in[8];
    const float* W_v    = (const float*)d_in[9];
    const float* Wc_qk  = (const float*)d_in[10];
    const float* Wc_v   = (const float*)d_in[11];
    const float* W_out  = (const float*)d_in[12];
    const float* b_out  = (const float*)d_in[13];
    const float* Wc_out = (const float*)d_in[14];
    const float* bc_out = (const float*)d_in[15];
    const float* ff_g   = (const float*)d_in[16];
    const float* ff_b   = (const float*)d_in[17];
    const float* ff_w1  = (const float*)d_in[18];
    const float* ff_b1  = (const float*)d_in[19];
    const float* ff_w2  = (const float*)d_in[20];
    const float* ff_b2  = (const float*)d_in[21];
    const float* cff_g  = (const float*)d_in[22];
    const float* cff_b  = (const float*)d_in[23];
    const float* cff_w1 = (const float*)d_in[24];
    const float* cff_b1 = (const float*)d_in[25];
    const float* cff_w2 = (const float*)d_in[26];
    const float* cff_b2 = (const float*)d_in[27];
    float* outp = (float*)d_out;

    float *sim, *x1, *c1;
    bf16 *attn, *cattn, *qk, *v, *cqk, *cv, *out, *cout;
    bf16 *xnh, *xnl, *cnh, *cnl, *hh, *hl, *wph, *woh, *f1h, *f1l, *f2h, *f2l;
    cudaGetSymbolAddress((void**)&sim,   g_sim);
    cudaGetSymbolAddress((void**)&x1,    g_x1);
    cudaGetSymbolAddress((void**)&c1,    g_c1);
    cudaGetSymbolAddress((void**)&attn,  g_attn);
    cudaGetSymbolAddress((void**)&cattn, g_cattn);
    cudaGetSymbolAddress((void**)&qk,    g_qk);
    cudaGetSymbolAddress((void**)&v,     g_v);
    cudaGetSymbolAddress((void**)&cqk,   g_cqk);
    cudaGetSymbolAddress((void**)&cv,    g_cv);
    cudaGetSymbolAddress((void**)&out,   g_out);
    cudaGetSymbolAddress((void**)&cout,  g_cout);
    cudaGetSymbolAddress((void**)&xnh,   g_xnh);
    cudaGetSymbolAddress((void**)&xnl,   g_xnl);
    cudaGetSymbolAddress((void**)&cnh,   g_cnh);
    cudaGetSymbolAddress((void**)&cnl,   g_cnl);
    cudaGetSymbolAddress((void**)&hh,    g_hh);
    cudaGetSymbolAddress((void**)&hl,    g_hl);
    cudaGetSymbolAddress((void**)&wph,   g_wph);
    cudaGetSymbolAddress((void**)&woh,   g_woh);
    cudaGetSymbolAddress((void**)&f1h,   g_f1h);
    cudaGetSymbolAddress((void**)&f1l,   g_f1l);
    cudaGetSymbolAddress((void**)&f2h,   g_f2h);
    cudaGetSymbolAddress((void**)&f2l,   g_f2l);

    const float SCALE = 0.125f;
    const long PW = (long)INNERi * Dd;
    const long FW = (long)FFDf * Dd;
    const bf16* nb = nullptr;
    bf16* nbm = nullptr;
    const float* nf = nullptr;

    detect_mask_mode<<<1, 256>>>((const float*)mask, (Bb * Nn) / 4);
    wt_prep<false><<<dim3(INNERi / 32, Dd / 32), 256>>>(W_qk,  wph + 0 * PW, nullptr, Dd, INNERi);
    wt_prep<false><<<dim3(INNERi / 32, Dd / 32), 256>>>(W_v,   wph + 1 * PW, nullptr, Dd, INNERi);
    wt_prep<false><<<dim3(INNERi / 32, Dd / 32), 256>>>(Wc_qk, wph + 2 * PW, nullptr, Dd, INNERi);
    wt_prep<false><<<dim3(INNERi / 32, Dd / 32), 256>>>(Wc_v,  wph + 3 * PW, nullptr, Dd, INNERi);
    wt_prep<false><<<dim3(Dd / 32, INNERi / 32), 256>>>(W_out,  woh + 0 * PW, nullptr, INNERi, Dd);
    wt_prep<false><<<dim3(Dd / 32, INNERi / 32), 256>>>(Wc_out, woh + 1 * PW, nullptr, INNERi, Dd);
    wt_prep<true><<<dim3(FFDf / 32, Dd / 32), 256>>>(ff_w1,  f1h + 0 * FW, f1l + 0 * FW, Dd, FFDf);
    wt_prep<true><<<dim3(FFDf / 32, Dd / 32), 256>>>(cff_w1, f1h + 1 * FW, f1l + 1 * FW, Dd, FFDf);
    wt_prep<true><<<dim3(Dd / 32, FFDf / 32), 256>>>(ff_w2,  f2h + 0 * FW, f2l + 0 * FW, FFDf, Dd);
    wt_prep<true><<<dim3(Dd / 32, FFDf / 32), 256>>>(cff_w2, f2h + 1 * FW, f2l + 1 * FW, FFDf, Dd);

    ln_bf<<<Bb * Nn,  256>>>(x,   ln_x_g, ln_x_b, xnh, xnl, Dd);
    ln_bf<<<Bb * MM_, 256>>>(ctx, ln_c_g, ln_c_b, cnh, cnl, Dd);

    // projections: 128x128 tiles
    LGB(128, 128, false, true, 1, 1, dim3(INNERi / 128, Bb * Nn / 128, 1),
        xnh, nb, Dd, 0, 0, wph + 0 * PW, nb, Dd, 0, 0,
        (float*)nullptr, qk, nbm, INNERi, 0, 0, nf, nf, 0, Dd, 1.f, 1);
    LGB(128, 128, false, true, 1, 1, dim3(INNERi / 128, Bb * Nn / 128, 1),
        xnh, nb, Dd, 0, 0, wph + 1 * PW, nb, Dd, 0, 0,
        (float*)nullptr, v, nbm, INNERi, 0, 0, nf, nf, 0, Dd, 1.f, 1);
    LGB(128, 128, false, true, 1, 1, dim3(INNERi / 128, Bb * MM_ / 128, 1),
        cnh, nb, Dd, 0, 0, wph + 2 * PW, nb, Dd, 0, 0,
        (float*)nullptr, cqk, nbm, INNERi, 0, 0, nf, nf, 0, Dd, 1.f, 1);
    LGB(128, 128, false, true, 1, 1, dim3(INNERi / 128, Bb * MM_ / 128, 1),
        cnh, nb, Dd, 0, 0, wph + 3 * PW, nb, Dd, 0, 0,
        (float*)nullptr, cv, nbm, INNERi, 0, 0, nf, nf, 0, Dd, 1.f, 1);

    // sim = qk @ cqk^T * SCALE (f32 out, batched b*h)
    LGB(128, 128, false, true, 1, 0, dim3(MM_ / 128, Nn / 128, Bb * Hh),
        qk, nb, INNERi, (long)Nn * INNERi, DHd,
        cqk, nb, INNERi, (long)MM_ * INNERi, DHd,
        sim, nbm, nbm, MM_, (long)Hh * Nn * MM_, (long)Nn * MM_,
        nf, nf, 0, DHd, SCALE, Hh);

    softmax_row<<<Bb * Hh * Nn, 256>>>(sim, attn, mask, cmask);
    softmax_col<<<dim3(MM_ / 32, Bb * Hh), 256>>>(sim, cattn, mask, cmask);

    // PV: out = attn @ cv ; cout = cattn^T @ v (bf16 out)
    LGB(64, 64, false, false, 1, 1, dim3(1, Nn / 64, Bb * Hh),
        attn, nb, MM_, (long)Hh * Nn * MM_, (long)Nn * MM_,
        cv, nb, INNERi, (long)MM_ * INNERi, DHd,
        (float*)nullptr, out, nbm, INNERi, (long)Nn * INNERi, DHd,
        nf, nf, 0, MM_, 1.f, Hh);
    LGB(64, 64, true, false, 1, 1, dim3(1, MM_ / 64, Bb * Hh),
        cattn, nb, MM_, (long)Hh * Nn * MM_, (long)Nn * MM_,
        v, nb, INNERi, (long)Nn * INNERi, DHd,
        (float*)nullptr, cout, nbm, INNERi, (long)MM_ * INNERi, DHd,
        nf, nf, 0, Nn, 1.f, Hh);

    // out-proj + residual (f32)
    LGB(128, 128, false, true, 1, 2, dim3(Dd / 128, Bb * Nn / 128, 1),
        out, nb, INNERi, 0, 0, woh + 0 * PW, nb, INNERi, 0, 0,
        x1, nbm, nbm, Dd, 0, 0, b_out, x, Dd, INNERi, 1.f, 1);
    LGB(128, 128, false, true, 1, 2, dim3(Dd / 128, Bb * MM_ / 128, 1),
        cout, nb, INNERi, 0, 0, woh + 1 * PW, nb, INNERi, 0, 0,
        c1, nbm, nbm, Dd, 0, 0, bc_out, ctx, Dd, INNERi, 1.f, 1);

    // FFN x-side (3-term split bf16)
    ln_bf<<<Bb * Nn, 256>>>(x1, ff_g, ff_b, xnh, xnl, Dd);
    LGB(128, 128, false, true, 3, 3, dim3(FFDf / 128, Bb * Nn / 128, 1),
        xnh, xnl, Dd, 0, 0, f1h + 0 * FW, f1l + 0 * FW, Dd, 0, 0,
        (float*)nullptr, hh, hl, FFDf, 0, 0, ff_b1, nf, 0, Dd, 1.f, 1);
    LGB(128, 128, false, true, 3, 2, dim3(Dd / 128, Bb * Nn / 128, 1),
        hh, hl, FFDf, 0, 0, f2h + 0 * FW, f2l + 0 * FW, FFDf, 0, 0,
        outp, nbm, nbm, Dd, 0, 0, ff_b2, x1, Dd, FFDf, 1.f, 1);

    // FFN context-side
    ln_bf<<<Bb * MM_, 256>>>(c1, cff_g, cff_b, cnh, cnl, Dd);
    LGB(128, 128, false, true, 3, 3, dim3(FFDf / 128, Bb * MM_ / 128, 1),
        cnh, cnl, Dd, 0, 0, f1h + 1 * FW, f1l + 1 * FW, Dd, 0, 0,
        (float*)nullptr, hh, hl, FFDf, 0, 0, cff_b1, nf, 0, Dd, 1.f, 1);
    LGB(128, 128, false, true, 3, 2, dim3(Dd / 128, Bb * MM_ / 128, 1),
        hh, hl, FFDf, 0, 0, f2h + 1 * FW, f2l + 1 * FW, FFDf, 0, 0,
        outp + (long)Bb * Nn * Dd, nbm, nbm, Dd, 0, 0, cff_b2, c1, Dd, FFDf, 1.f, 1);
}

// round 11
// speedup vs baseline: 1.4066x; 1.0213x over previous
#include <cuda_runtime.h>
#include <cuda_bf16.h>
#include <mma.h>
#include <math.h>
#include <cstdint>

using namespace nvcuda;
typedef __nv_bfloat16 bf16;

#define Bb 2
#define Nn 2048
#define MM_ 2048
#define Dd 1024
#define Hh 8
#define DHd 64
#define INNERi 512
#define FFDf 4096

// ---------------- scratch ----------------------------------------------------
__device__ __align__(256) float g_x1  [Bb*Nn*Dd];
__device__ __align__(256) float g_c1  [Bb*MM_*Dd];
__device__ __align__(256) bf16 g_simb [Bb*Hh*Nn*MM_];
__device__ __align__(256) bf16 g_attn [Bb*Hh*Nn*MM_];
__device__ __align__(256) bf16 g_cattn[Bb*Hh*Nn*MM_];
__device__ __align__(256) bf16 g_qk [Bb*Nn*INNERi];
__device__ __align__(256) bf16 g_v  [Bb*Nn*INNERi];
__device__ __align__(256) bf16 g_cqk[Bb*MM_*INNERi];
__device__ __align__(256) bf16 g_cv [Bb*MM_*INNERi];
__device__ __align__(256) bf16 g_out [Bb*Nn*INNERi];
__device__ __align__(256) bf16 g_cout[Bb*MM_*INNERi];
__device__ __align__(256) bf16 g_xnh[Bb*Nn*Dd];
__device__ __align__(256) bf16 g_xnl[Bb*Nn*Dd];
__device__ __align__(256) bf16 g_cnh[Bb*MM_*Dd];
__device__ __align__(256) bf16 g_cnl[Bb*MM_*Dd];
__device__ __align__(256) bf16 g_hh[Bb*Nn*FFDf];
__device__ __align__(256) bf16 g_hl[Bb*Nn*FFDf];
__device__ __align__(256) bf16 g_wph[4*INNERi*Dd];
__device__ __align__(256) bf16 g_woh[2*Dd*INNERi];
__device__ __align__(256) bf16 g_f1h[2*FFDf*Dd];
__device__ __align__(256) bf16 g_f1l[2*FFDf*Dd];
__device__ __align__(256) bf16 g_f2h[2*Dd*FFDf];
__device__ __align__(256) bf16 g_f2l[2*Dd*FFDf];
__device__ int g_mask_mode;

// ---------------- mask detection ---------------------------------------------
__global__ void detect_mask_mode(const float* __restrict__ fp, int n4)
{
    __shared__ int okf_s, oki_s;
    if (threadIdx.x == 0) { okf_s = 1; oki_s = 1; }
    __syncthreads();
    const int* ip = (const int*)fp;
    bool okf = true, oki = true;
    for (int i = threadIdx.x; i < n4; i += 256) {
        float fv = fp[i]; okf = okf && (fv == 0.f || fv == 1.f);
        int   iv = ip[i]; oki = oki && (iv == 0 || iv == 1);
    }
    if (!okf) atomicAnd(&okf_s, 0);
    if (!oki) atomicAnd(&oki_s, 0);
    __syncthreads();
    if (threadIdx.x == 0) g_mask_mode = okf_s ? 2 : (oki_s ? 1 : 0);
}
__device__ __forceinline__ bool mask_at(const void* m, int i, int mode)
{
    if (mode == 1) return ((const int*)m)[i] != 0;
    if (mode == 2) return ((const float*)m)[i] != 0.f;
    return ((const unsigned char*)m)[i] != 0;
}

// ---------------- LayerNorm -> bf16 hi/lo ------------------------------------
__global__ __launch_bounds__(256)
void ln_bf(const float* __restrict__ in, const float* __restrict__ g,
           const float* __restrict__ b, bf16* __restrict__ oh,
           bf16* __restrict__ ol, int cols)
{
    __shared__ float r1[256], r2[256];
    long row = blockIdx.x;
    const float* p = in + row * cols;
    bf16* ph = oh + row * cols;
    bf16* pl = ol + row * cols;
    int tid = threadIdx.x;
    float s = 0.f, s2 = 0.f;
    for (int c = tid; c < cols; c += 256) { float v = p[c]; s += v; s2 += v * v; }
    r1[tid] = s; r2[tid] = s2; __syncthreads();
    for (int st = 128; st > 0; st >>= 1) {
        if (tid < st) { r1[tid] += r1[tid + st]; r2[tid] += r2[tid + st]; }
        __syncthreads();
    }
    float mu  = r1[0] / cols;
    float var = r2[0] / cols - mu * mu;
    float inv = rsqrtf(var + 1e-5f);
    for (int c = tid; c < cols; c += 256) {
        float y = (p[c] - mu) * inv * g[c] + b[c];
        bf16 hv = __float2bfloat16(y);
        ph[c] = hv;
        pl[c] = __float2bfloat16(y - __bfloat162float(hv));
    }
}

// ---------------- dual softmax (bf16 sim, bf16 outputs) ------------------------
__global__ __launch_bounds__(256)
void softmax_row(const bf16* __restrict__ sim, bf16* __restrict__ attn,
                 const void* __restrict__ mask, const void* __restrict__ cmask)
{
    __shared__ float buf[MM_];
    __shared__ float red[256];
    int mode = g_mask_mode;
    long row = blockIdx.x;
    int i = (int)(row % Nn), bh = (int)(row / Nn), b = bh / Hh;
    const bf16* src = sim  + row * (long)MM_;
    bf16*       dst = attn + row * (long)MM_;
    int tid = threadIdx.x;
    bool mi = mask_at(mask, b * Nn + i, mode);
    float lmax = -3.402823466e38f;
    for (int j = tid; j < MM_; j += 256) {
        bool mj = mask_at(cmask, b * MM_ + j, mode);
        float vv = (mi && mj) ? __bfloat162float(src[j]) : -3.402823466e38f;
        buf[j] = vv; lmax = fmaxf(lmax, vv);
    }
    red[tid] = lmax; __syncthreads();
    for (int s = 128; s > 0; s >>= 1) {
        if (tid < s) red[tid] = fmaxf(red[tid], red[tid + s]);
        __syncthreads();
    }
    float rmax = red[0]; __syncthreads();
    float lsum = 0.f;
    for (int j = tid; j < MM_; j += 256) { float e = expf(buf[j] - rmax); buf[j] = e; lsum += e; }
    red[tid] = lsum; __syncthreads();
    for (int s = 128; s > 0; s >>= 1) {
        if (tid < s) red[tid] += red[tid + s];
        __syncthreads();
    }
    float inv = 1.f / red[0];
    for (int j = tid; j < MM_; j += 256) dst[j] = __float2bfloat16(buf[j] * inv);
}

__global__ __launch_bounds__(256)
void softmax_col(const bf16* __restrict__ sim, bf16* __restrict__ cattn,
                 const void* __restrict__ mask, const void* __restrict__ cmask)
{
    __shared__ float sm[8][32], ss[8][32];
    int mode = g_mask_mode;
    int z = blockIdx.y, b = z / Hh;
    int c = threadIdx.x & 31, g = threadIdx.x >> 5;
    int j = blockIdx.x * 32 + c;
    const bf16* base = sim   + (long)z * Nn * MM_;
    bf16*       outb = cattn + (long)z * Nn * MM_;
    bool mj = mask_at(cmask, b * MM_ + j, mode);
    float m = -3.402823466e38f, s = 0.f;
    for (int i = g; i < Nn; i += 8) {
        bool mi = mask_at(mask, b * Nn + i, mode);
        float vv = (mj && mi) ? __bfloat162float(base[(long)i * MM_ + j]) : -3.402823466e38f;
        if (vv > m) { s = s * expf(m - vv) + 1.f; m = vv; }
        else        { s += expf(vv - m); }
    }
    sm[g][c] = m; ss[g][c] = s; __syncthreads();
    if (g == 0) {
        float Ml = sm[0][c], Sl = ss[0][c];
        #pragma unroll
        for (int t = 1; t < 8; t++) {
            float mt = sm[t][c], st = ss[t][c];
            float nm = fmaxf(Ml, mt);
            Sl = Sl * expf(Ml - nm) + st * expf(mt - nm);
            Ml = nm;
        }
        sm[0][c] = Ml; ss[0][c] = 1.f / Sl;
    }
    __syncthreads();
    float Mg = sm[0][c], inv = ss[0][c];
    for (int i = g; i < Nn; i += 8) {
        bool mi = mask_at(mask, b * Nn + i, mode);
        float vv = (mj && mi) ? __bfloat162float(base[(long)i * MM_ + j]) : -3.402823466e38f;
        outb[(long)i * MM_ + j] = __float2bfloat16(expf(vv - Mg) * inv);
    }
}

// ---------------- weight transpose + bf16 split -------------------------------
template<bool SPLIT>
__global__ __launch_bounds__(256)
void wt_prep(const float* __restrict__ W, bf16* __restrict__ Th,
             bf16* __restrict__ Tl, int K, int N)
{
    __shared__ float t[32][33];
    int n0 = blockIdx.x * 32, k0 = blockIdx.y * 32;
    int tx = threadIdx.x & 31, ty = threadIdx.x >> 5;
    #pragma unroll
    for (int i = 0; i < 4; i++)
        t[ty + i * 8][tx] = W[(long)(k0 + ty + i * 8) * N + n0 + tx];
    __syncthreads();
    #pragma unroll
    for (int i = 0; i < 4; i++) {
        float v = t[tx][ty + i * 8];
        long o = (long)(n0 + ty + i * 8) * K + k0 + tx;
        bf16 hv = __float2bfloat16(v);
        Th[o] = hv;
        if (SPLIT) Tl[o] = __float2bfloat16(v - __bfloat162float(hv));
    }
}

// ---------------- bf16 WMMA GEMM, 3-stage cp.async ----------------------------
// C = alpha * op(A) @ op(B)  with A [M,K] (or [K,M] if AC), B [K,N] (or [N,K] if BC).
// NT=1: hi operands only. NT=3: Ah*Bh + Ah*Bl + Al*Bh (split bf16, ~16-bit).
// EPI: 0 = f32 direct frag store (alpha); 1 = bf16 hi out (alpha);
//      2 = f32 + bias + res;  3 = GELU(v+bias) -> bf16 hi/lo.
__device__ __forceinline__ void cpab(uint32_t s, const void* g)
{ asm volatile("cp.async.cg.shared.global [%0], [%1], 16;\n" :: "r"(s), "l"(g)); }

template<int BM, int BN, bool AC, bool BC, int NT, int EPI>
__global__ __launch_bounds__(256)
void gbf(const bf16* __restrict__ Ah, const bf16* __restrict__ Al, int lda, long aO, long aI,
         const bf16* __restrict__ Bh, const bf16* __restrict__ Bl, int ldb, long bO, long bI,
         float* __restrict__ C, bf16* __restrict__ Cbh, bf16* __restrict__ Cbl,
         int ldc, long cO, long cI,
         const float* __restrict__ bias, const float* __restrict__ res, int ldr,
         int K, float alpha, int HHd)
{
    constexpr int BK   = 32;
    constexpr int LDAS = AC ? BM + 8 : BK + 8;
    constexpr int AEL  = AC ? BK * LDAS : BM * LDAS;
    constexpr int LDBS = BC ? BK + 8 : BN + 8;
    constexpr int BEL  = BC ? BN * LDBS : BK * LDBS;
    constexpr int NM   = (NT == 3) ? 2 : 1;
    constexpr int SEL  = NM * (AEL + BEL);
    constexpr int WRM  = (BN == 128) ? 2 : 4;
    constexpr int WRN  = 8 / WRM;
    constexpr int TM   = BM / WRM, TN = BN / WRN;
    constexpr int FM   = TM / 16, FN = TN / 16;
    constexpr int oAl  = AEL;
    constexpr int oBh  = NM * AEL;
    constexpr int oBl  = NM * AEL + BEL;

    extern __shared__ bf16 smb_[];
    uint32_t sb0;
    asm("{ .reg .u64 t; cvta.to.shared.u64 t, %1; cvt.u32.u64 %0, t; }"
        : "=r"(sb0) : "l"(smb_));

    int z = blockIdx.z, zo = z / HHd, zi = z % HHd;
    Ah += (long)zo * aO + (long)zi * aI;
    Bh += (long)zo * bO + (long)zi * bI;
    if (NT == 3) { Al += (long)zo * aO + (long)zi * aI; Bl += (long)zo * bO + (long)zi * bI; }
    long m0 = (long)blockIdx.y * BM, n0 = (long)blockIdx.x * BN;
    int tid = threadIdx.x, warp = tid >> 5;
    int wm0 = (warp % WRM) * TM, wn0 = (warp / WRM) * TN;

    auto load_stage = [&](int s, int kt) {
        uint32_t base = sb0 + (uint32_t)(s * SEL * 2);
        int kb = kt * BK;
        if (!AC) {
            constexpr int C8 = BK / 8, TOT = BM * C8;
            for (int idx = tid; idx < TOT; idx += 256) {
                int r = idx / C8, c = idx % C8;
                uint32_t o = base + (uint32_t)((r * LDAS + c * 8) * 2);
                cpab(o, Ah + (m0 + r) * (long)lda + kb + c * 8);
                if (NT == 3) cpab(o + (uint32_t)(oAl * 2), Al + (m0 + r) * (long)lda + kb + c * 8);
            }
        } else {
            constexpr int C8 = BM / 8, TOT = BK * C8;
            for (int idx = tid; idx < TOT; idx += 256) {
                int k = idx / C8, mc = idx % C8;
                uint32_t o = base + (uint32_t)((k * LDAS + mc * 8) * 2);
                cpab(o, Ah + (long)(kb + k) * lda + m0 + mc * 8);
                if (NT == 3) cpab(o + (uint32_t)(oAl * 2), Al + (long)(kb + k) * lda + m0 + mc * 8);
            }
        }
        if (BC) {
            constexpr int C8 = BK / 8, TOT = BN * C8;
            for (int idx = tid; idx < TOT; idx += 256) {
                int n = idx / C8, c = idx % C8;
                uint32_t o = base + (uint32_t)((oBh + n * LDBS + c * 8) * 2);
                cpab(o, Bh + (n0 + n) * (long)ldb + kb + c * 8);
                if (NT == 3) cpab(o + (uint32_t)((oBl - oBh) * 2), Bl + (n0 + n) * (long)ldb + kb + c * 8);
            }
        } else {
            constexpr int C8 = BN / 8, TOT = BK * C8;
            for (int idx = tid; idx < TOT; idx += 256) {
                int k = idx / C8, c = idx % C8;
                uint32_t o = base + (uint32_t)((oBh + k * LDBS + c * 8) * 2);
                cpab(o, Bh + (long)(kb + k) * ldb + n0 + c * 8);
                if (NT == 3) cpab(o + (uint32_t)((oBl - oBh) * 2), Bl + (long)(kb + k) * ldb + n0 + c * 8);
            }
        }
        asm volatile("cp.async.commit_group;\n");
    };

    using ALay = typename std::conditional<AC, wmma::col_major, wmma::row_major>::type;
    using BLay = typename std::conditional<BC, wmma::col_major, wmma::row_major>::type;
    wmma::fragment<wmma::accumulator, 16, 16, 16, float> fc[FM][FN];
    #pragma unroll
    for (int i = 0; i < FM; i++)
        #pragma unroll
        for (int j = 0; j < FN; j++)
            wmma::fill_fragment(fc[i][j], 0.f);

    int T = K / BK;
    load_stage(0, 0);
    if (T > 1) load_stage(1, 1);

    for (int kt = 0; kt < T; kt++) {
        if (kt + 1 < T) asm volatile("cp.async.wait_group 1;\n");
        else            asm volatile("cp.async.wait_group 0;\n");
        __syncthreads();
        if (kt + 2 < T) load_stage((kt + 2) % 3, kt + 2);

        const bf16* st = smb_ + (kt % 3) * SEL;
        const bf16* sAh = st;
        const bf16* sAl = st + oAl;
        const bf16* sBh = st + oBh;
        const bf16* sBl = st + oBl;

        #pragma unroll
        for (int kk = 0; kk < BK; kk += 16) {
            wmma::fragment<wmma::matrix_a, 16, 16, 16, bf16, ALay> fa[FM], fal[FM];
            wmma::fragment<wmma::matrix_b, 16, 16, 16, bf16, BLay> fb[FN], fbl[FN];
            #pragma unroll
            for (int i = 0; i < FM; i++) {
                const bf16* ap = AC ? (sAh + kk * LDAS + wm0 + i * 16)
                                    : (sAh + (wm0 + i * 16) * LDAS + kk);
                wmma::load_matrix_sync(fa[i], ap, LDAS);
                if (NT == 3) {
                    const bf16* ap2 = AC ? (sAl + kk * LDAS + wm0 + i * 16)
                                         : (sAl + (wm0 + i * 16) * LDAS + kk);
                    wmma::load_matrix_sync(fal[i], ap2, LDAS);
                }
            }
            #pragma unroll
            for (int j = 0; j < FN; j++) {
                const bf16* bp = BC ? (sBh + (wn0 + j * 16) * LDBS + kk)
                                    : (sBh + kk * LDBS + wn0 + j * 16);
                wmma::load_matrix_sync(fb[j], bp, LDBS);
                if (NT == 3) {
                    const bf16* bp2 = BC ? (sBl + (wn0 + j * 16) * LDBS + kk)
                                         : (sBl + kk * LDBS + wn0 + j * 16);
                    wmma::load_matrix_sync(fbl[j], bp2, LDBS);
                }
            }
            #pragma unroll
            for (int i = 0; i < FM; i++)
                #pragma unroll
                for (int j = 0; j < FN; j++) {
                    if (NT == 3) {
                        wmma::mma_sync(fc[i][j], fa[i], fbl[j], fc[i][j]);
                        wmma::mma_sync(fc[i][j], fal[i], fb[j], fc[i][j]);
                    }
                    wmma::mma_sync(fc[i][j], fa[i], fb[j], fc[i][j]);
                }
        }
    }

    if (EPI == 0) {
        #pragma unroll
        for (int i = 0; i < FM; i++)
            #pragma unroll
            for (int j = 0; j < FN; j++) {
                #pragma unroll
                for (int t = 0; t < fc[i][j].num_elements; t++)
                    fc[i][j].x[t] *= alpha;
                wmma::store_matrix_sync(
                    C + (long)zo * cO + (long)zi * cI +
                        (m0 + wm0 + i * 16) * (long)ldc + n0 + wn0 + j * 16,
                    fc[i][j], ldc, wmma::mem_row_major);
            }
        return;
    }

    __syncthreads();
    float* sC = (float*)smb_;
    constexpr int LDCS = BN + 4;
    #pragma unroll
    for (int i = 0; i < FM; i++)
        #pragma unroll
        for (int j = 0; j < FN; j++)
            wmma::store_matrix_sync(sC + (wm0 + i * 16) * LDCS + wn0 + j * 16,
                                    fc[i][j], LDCS, wmma::mem_row_major);
    __syncthreads();
    constexpr int NB4 = BN / 4;
    for (int idx = tid; idx < BM * NB4; idx += 256) {
        int r = idx / NB4, c4 = (idx % NB4) * 4;
        long gm = m0 + r, gn = n0 + c4;
        long cb = (long)zo * cO + (long)zi * cI;
        float v0 = sC[r * LDCS + c4 + 0], v1 = sC[r * LDCS + c4 + 1];
        float v2 = sC[r * LDCS + c4 + 2], v3 = sC[r * LDCS + c4 + 3];
        if (EPI == 1) {
            __nv_bfloat162 p0, p1;
            p0.x = __float2bfloat16(v0 * alpha); p0.y = __float2bfloat16(v1 * alpha);
            p1.x = __float2bfloat16(v2 * alpha); p1.y = __float2bfloat16(v3 * alpha);
            ((__nv_bfloat162*)(Cbh + cb + gm * ldc + gn))[0] = p0;
            ((__nv_bfloat162*)(Cbh + cb + gm * ldc + gn))[1] = p1;
        } else if (EPI == 2) {
            float4 bb = *(const float4*)(bias + gn);
            float4 rr = *(const float4*)(res + gm * (long)ldr + gn);
            float4 o = { v0 + bb.x + rr.x, v1 + bb.y + rr.y,
                         v2 + bb.z + rr.z, v3 + bb.w + rr.w };
            *(float4*)(C + cb + gm * ldc + gn) = o;
        } else {
            float4 bb = *(const float4*)(bias + gn);
            float t0 = v0 + bb.x, t1 = v1 + bb.y, t2 = v2 + bb.z, t3 = v3 + bb.w;
            t0 = 0.5f * t0 * (1.f + erff(t0 * 0.7071067811865476f));
            t1 = 0.5f * t1 * (1.f + erff(t1 * 0.7071067811865476f));
            t2 = 0.5f * t2 * (1.f + erff(t2 * 0.7071067811865476f));
            t3 = 0.5f * t3 * (1.f + erff(t3 * 0.7071067811865476f));
            bf16 h0 = __float2bfloat16(t0), h1 = __float2bfloat16(t1);
            bf16 h2 = __float2bfloat16(t2), h3 = __float2bfloat16(t3);
            __nv_bfloat162 hp0, hp1, lp0, lp1;
            hp0.x = h0; hp0.y = h1; hp1.x = h2; hp1.y = h3;
            lp0.x = __float2bfloat16(t0 - __bfloat162float(h0));
            lp0.y = __float2bfloat16(t1 - __bfloat162float(h1));
            lp1.x = __float2bfloat16(t2 - __bfloat162float(h2));
            lp1.y = __float2bfloat16(t3 - __bfloat162float(h3));
            ((__nv_bfloat162*)(Cbh + gm * ldc + gn))[0] = hp0;
            ((__nv_bfloat162*)(Cbh + gm * ldc + gn))[1] = hp1;
            ((__nv_bfloat162*)(Cbl + gm * ldc + gn))[0] = lp0;
            ((__nv_bfloat162*)(Cbl + gm * ldc + gn))[1] = lp1;
        }
    }
}

static constexpr size_t gsm(int BM, int BN, bool AC, bool BC, int NT)
{
    int LDAS = AC ? BM + 8 : 40;
    int AEL  = AC ? 32 * LDAS : BM * LDAS;
    int LDBS = BC ? 40 : BN + 8;
    int BEL  = BC ? BN * LDBS : 32 * LDBS;
    int NM   = (NT == 3) ? 2 : 1;
    size_t pipe = 3u * 2u * (size_t)(NM * (AEL + BEL));
    size_t epi  = 4u * (size_t)BM * (BN + 4);
    return pipe > epi ? pipe : epi;
}

#define LGB(BM, BN, AC, BC, NT, EPI, grid, ...)                                  \
    do {                                                                         \
        auto kfn = gbf<BM, BN, AC, BC, NT, EPI>;                                 \
        size_t smb = gsm(BM, BN, AC, BC, NT);                                    \
        cudaFuncSetAttribute(kfn, cudaFuncAttributeMaxDynamicSharedMemorySize, (int)smb); \
        kfn<<<grid, 256, smb>>>(__VA_ARGS__);                                    \
    } while (0)

// ---------------- host ----------------------------------------------------------
extern "C" void kernel_launch(void* const* d_in, const int* in_sizes, int n_in,
                              void* d_out, int out_size)
{
    (void)in_sizes; (void)n_in; (void)out_size;
    const float* x      = (const float*)d_in[0];
    const float* ctx    = (const float*)d_in[1];
    const void*  mask   = d_in[2];
    const void*  cmask  = d_in[3];
    const float* ln_x_g = (const float*)d_in[4];
    const float* ln_x_b = (const float*)d_in[5];
    const float* ln_c_g = (const float*)d_in[6];
    const float* ln_c_b = (const float*)d_in[7];
    const float* W_qk   = (const float*)d_in[8];
    const float* W_v    = (const float*)d_in[9];
    const float* Wc_qk  = (const float*)d_in[10];
    const float* Wc_v   = (const float*)d_in[11];
    const float* W_out  = (const float*)d_in[12];
    const float* b_out  = (const float*)d_in[13];
    const float* Wc_out = (const float*)d_in[14];
    const float* bc_out = (const float*)d_in[15];
    const float* ff_g   = (const float*)d_in[16];
    const float* ff_b   = (const float*)d_in[17];
    const float* ff_w1  = (const float*)d_in[18];
    const float* ff_b1  = (const float*)d_in[19];
    const float* ff_w2  = (const float*)d_in[20];
    const float* ff_b2  = (const float*)d_in[21];
    const float* cff_g  = (const float*)d_in[22];
    const float* cff_b  = (const float*)d_in[23];
    const float* cff_w1 = (const float*)d_in[24];
    const float* cff_b1 = (const float*)d_in[25];
    const float* cff_w2 = (const float*)d_in[26];
    const float* cff_b2 = (const float*)d_in[27];
    float* outp = (float*)d_out;

    float *x1, *c1;
    bf16 *simb, *attn, *cattn, *qk, *v, *cqk, *cv, *out, *cout;
    bf16 *xnh, *xnl, *cnh, *cnl, *hh, *hl, *wph, *woh, *f1h, *f1l, *f2h, *f2l;
    cudaGetSymbolAddress((void**)&x1,    g_x1);
    cudaGetSymbolAddress((void**)&c1,    g_c1);
    cudaGetSymbolAddress((void**)&simb,  g_simb);
    cudaGetSymbolAddress((void**)&attn,  g_attn);
    cudaGetSymbolAddress((void**)&cattn, g_cattn);
    cudaGetSymbolAddress((void**)&qk,    g_qk);
    cudaGetSymbolAddress((void**)&v,     g_v);
    cudaGetSymbolAddress((void**)&cqk,   g_cqk);
    cudaGetSymbolAddress((void**)&cv,    g_cv);
    cudaGetSymbolAddress((void**)&out,   g_out);
    cudaGetSymbolAddress((void**)&cout,  g_cout);
    cudaGetSymbolAddress((void**)&xnh,   g_xnh);
    cudaGetSymbolAddress((void**)&xnl,   g_xnl);
    cudaGetSymbolAddress((void**)&cnh,   g_cnh);
    cudaGetSymbolAddress((void**)&cnl,   g_cnl);
    cudaGetSymbolAddress((void**)&hh,    g_hh);
    cudaGetSymbolAddress((void**)&hl,    g_hl);
    cudaGetSymbolAddress((void**)&wph,   g_wph);
    cudaGetSymbolAddress((void**)&woh,   g_woh);
    cudaGetSymbolAddress((void**)&f1h,   g_f1h);
    cudaGetSymbolAddress((void**)&f1l,   g_f1l);
    cudaGetSymbolAddress((void**)&f2h,   g_f2h);
    cudaGetSymbolAddress((void**)&f2l,   g_f2l);

    const float SCALE = 0.125f;
    const long PW = (long)INNERi * Dd;
    const long FW = (long)FFDf * Dd;
    const bf16* nb = nullptr;
    bf16* nbm = nullptr;
    const float* nf = nullptr;

    detect_mask_mode<<<1, 256>>>((const float*)mask, (Bb * Nn) / 4);
    wt_prep<false><<<dim3(INNERi / 32, Dd / 32), 256>>>(W_qk,  wph + 0 * PW, nullptr, Dd, INNERi);
    wt_prep<false><<<dim3(INNERi / 32, Dd / 32), 256>>>(W_v,   wph + 1 * PW, nullptr, Dd, INNERi);
    wt_prep<false><<<dim3(INNERi / 32, Dd / 32), 256>>>(Wc_qk, wph + 2 * PW, nullptr, Dd, INNERi);
    wt_prep<false><<<dim3(INNERi / 32, Dd / 32), 256>>>(Wc_v,  wph + 3 * PW, nullptr, Dd, INNERi);
    wt_prep<false><<<dim3(Dd / 32, INNERi / 32), 256>>>(W_out,  woh + 0 * PW, nullptr, INNERi, Dd);
    wt_prep<false><<<dim3(Dd / 32, INNERi / 32), 256>>>(Wc_out, woh + 1 * PW, nullptr, INNERi, Dd);
    wt_prep<true><<<dim3(FFDf / 32, Dd / 32), 256>>>(ff_w1,  f1h + 0 * FW, f1l + 0 * FW, Dd, FFDf);
    wt_prep<true><<<dim3(FFDf / 32, Dd / 32), 256>>>(cff_w1, f1h + 1 * FW, f1l + 1 * FW, Dd, FFDf);
    wt_prep<true><<<dim3(Dd / 32, FFDf / 32), 256>>>(ff_w2,  f2h + 0 * FW, f2l + 0 * FW, FFDf, Dd);
    wt_prep<true><<<dim3(Dd / 32, FFDf / 32), 256>>>(cff_w2, f2h + 1 * FW, f2l + 1 * FW, FFDf, Dd);

    ln_bf<<<Bb * Nn,  256>>>(x,   ln_x_g, ln_x_b, xnh, xnl, Dd);
    ln_bf<<<Bb * MM_, 256>>>(ctx, ln_c_g, ln_c_b, cnh, cnl, Dd);

    // projections: 128x128 tiles, bf16 out
    LGB(128, 128, false, true, 1, 1, dim3(INNERi / 128, Bb * Nn / 128, 1),
        xnh, nb, Dd, 0, 0, wph + 0 * PW, nb, Dd, 0, 0,
        (float*)nullptr, qk, nbm, INNERi, 0, 0, nf, nf, 0, Dd, 1.f, 1);
    LGB(128, 128, false, true, 1, 1, dim3(INNERi / 128, Bb * Nn / 128, 1),
        xnh, nb, Dd, 0, 0, wph + 1 * PW, nb, Dd, 0, 0,
        (float*)nullptr, v, nbm, INNERi, 0, 0, nf, nf, 0, Dd, 1.f, 1);
    LGB(128, 128, false, true, 1, 1, dim3(INNERi / 128, Bb * MM_ / 128, 1),
        cnh, nb, Dd, 0, 0, wph + 2 * PW, nb, Dd, 0, 0,
        (float*)nullptr, cqk, nbm, INNERi, 0, 0, nf, nf, 0, Dd, 1.f, 1);
    LGB(128, 128, false, true, 1, 1, dim3(INNERi / 128, Bb * MM_ / 128, 1),
        cnh, nb, Dd, 0, 0, wph + 3 * PW, nb, Dd, 0, 0,
        (float*)nullptr, cv, nbm, INNERi, 0, 0, nf, nf, 0, Dd, 1.f, 1);

    // sim = qk @ cqk^T * SCALE -> bf16 (EPI 1 with alpha)
    LGB(128, 128, false, true, 1, 1, dim3(MM_ / 128, Nn / 128, Bb * Hh),
        qk, nb, INNERi, (long)Nn * INNERi, DHd,
        cqk, nb, INNERi, (long)MM_ * INNERi, DHd,
        (float*)nullptr, simb, nbm, MM_, (long)Hh * Nn * MM_, (long)Nn * MM_,
        nf, nf, 0, DHd, SCALE, Hh);

    softmax_row<<<Bb * Hh * Nn, 256>>>(simb, attn, mask, cmask);
    softmax_col<<<dim3(MM_ / 32, Bb * Hh), 256>>>(simb, cattn, mask, cmask);

    // PV: 128x64 tiles (warp tile 32x32, 1:1 load:MMA)
    LGB(128, 64, false, false, 1, 1, dim3(1, Nn / 128, Bb * Hh),
        attn, nb, MM_, (long)Hh * Nn * MM_, (long)Nn * MM_,
        cv, nb, INNERi, (long)MM_ * INNERi, DHd,
        (float*)nullptr, out, nbm, INNERi, (long)Nn * INNERi, DHd,
        nf, nf, 0, MM_, 1.f, Hh);
    LGB(128, 64, true, false, 1, 1, dim3(1, MM_ / 128, Bb * Hh),
        cattn, nb, MM_, (long)Hh * Nn * MM_, (long)Nn * MM_,
        v, nb, INNERi, (long)Nn * INNERi, DHd,
        (float*)nullptr, cout, nbm, INNERi, (long)MM_ * INNERi, DHd,
        nf, nf, 0, Nn, 1.f, Hh);

    // out-proj + residual (f32)
    LGB(128, 128, false, true, 1, 2, dim3(Dd / 128, Bb * Nn / 128, 1),
        out, nb, INNERi, 0, 0, woh + 0 * PW, nb, INNERi, 0, 0,
        x1, nbm, nbm, Dd, 0, 0, b_out, x, Dd, INNERi, 1.f, 1);
    LGB(128, 128, false, true, 1, 2, dim3(Dd / 128, Bb * MM_ / 128, 1),
        cout, nb, INNERi, 0, 0, woh + 1 * PW, nb, INNERi, 0, 0,
        c1, nbm, nbm, Dd, 0, 0, bc_out, ctx, Dd, INNERi, 1.f, 1);

    // FFN x-side (3-term split bf16)
    ln_bf<<<Bb * Nn, 256>>>(x1, ff_g, ff_b, xnh, xnl, Dd);
    LGB(128, 128, false, true, 3, 3, dim3(FFDf / 128, Bb * Nn / 128, 1),
        xnh, xnl, Dd, 0, 0, f1h + 0 * FW, f1l + 0 * FW, Dd, 0, 0,
        (float*)nullptr, hh, hl, FFDf, 0, 0, ff_b1, nf, 0, Dd, 1.f, 1);
    LGB(128, 128, false, true, 3, 2, dim3(Dd / 128, Bb * Nn / 128, 1),
        hh, hl, FFDf, 0, 0, f2h + 0 * FW, f2l + 0 * FW, FFDf, 0, 0,
        outp, nbm, nbm, Dd, 0, 0, ff_b2, x1, Dd, FFDf, 1.f, 1);

    // FFN context-side
    ln_bf<<<Bb * MM_, 256>>>(c1, cff_g, cff_b, cnh, cnl, Dd);
    LGB(128, 128, false, true, 3, 3, dim3(FFDf / 128, Bb * MM_ / 128, 1),
        cnh, cnl, Dd, 0, 0, f1h + 1 * FW, f1l + 1 * FW, Dd, 0, 0,
        (float*)nullptr, hh, hl, FFDf, 0, 0, cff_b1, nf, 0, Dd, 1.f, 1);
    LGB(128, 128, false, true, 3, 2, dim3(Dd / 128, Bb * MM_ / 128, 1),
        hh, hl, FFDf, 0, 0, f2h + 1 * FW, f2l + 1 * FW, FFDf, 0, 0,
        outp + (long)Bb * Nn * Dd, nbm, nbm, Dd, 0, 0, cff_b2, c1, Dd, FFDf, 1.f, 1);
}

// round 12
// speedup vs baseline: 1.7552x; 1.2478x over previous
#include <cuda_runtime.h>
#include <cuda_fp16.h>
#include <mma.h>
#include <math.h>
#include <cstdint>

using namespace nvcuda;
typedef __half hf;

#define Bb 2
#define Nn 2048
#define MM_ 2048
#define Dd 1024
#define Hh 8
#define DHd 64
#define INNERi 512
#define FFDf 4096

// ---------------- scratch ----------------------------------------------------
__device__ __align__(256) float g_x1  [Bb*Nn*Dd];
__device__ __align__(256) float g_c1  [Bb*MM_*Dd];
__device__ __align__(256) hf g_simb [Bb*Hh*Nn*MM_];
__device__ __align__(256) hf g_attn [Bb*Hh*Nn*MM_];
__device__ __align__(256) hf g_cattn[Bb*Hh*Nn*MM_];
__device__ __align__(256) hf g_qk [Bb*Nn*INNERi];
__device__ __align__(256) hf g_v  [Bb*Nn*INNERi];
__device__ __align__(256) hf g_cqk[Bb*MM_*INNERi];
__device__ __align__(256) hf g_cv [Bb*MM_*INNERi];
__device__ __align__(256) hf g_out [Bb*Nn*INNERi];
__device__ __align__(256) hf g_cout[Bb*MM_*INNERi];
__device__ __align__(256) hf g_xn[Bb*Nn*Dd];
__device__ __align__(256) hf g_cn[Bb*MM_*Dd];
__device__ __align__(256) hf g_hb[Bb*Nn*FFDf];
__device__ __align__(256) hf g_wph[4*INNERi*Dd];
__device__ __align__(256) hf g_woh[2*Dd*INNERi];
__device__ __align__(256) hf g_f1h[2*FFDf*Dd];
__device__ __align__(256) hf g_f2h[2*Dd*FFDf];
__device__ int g_mask_mode;

// ---------------- mask detection ---------------------------------------------
__global__ void detect_mask_mode(const float* __restrict__ fp, int n4)
{
    __shared__ int okf_s, oki_s;
    if (threadIdx.x == 0) { okf_s = 1; oki_s = 1; }
    __syncthreads();
    const int* ip = (const int*)fp;
    bool okf = true, oki = true;
    for (int i = threadIdx.x; i < n4; i += 256) {
        float fv = fp[i]; okf = okf && (fv == 0.f || fv == 1.f);
        int   iv = ip[i]; oki = oki && (iv == 0 || iv == 1);
    }
    if (!okf) atomicAnd(&okf_s, 0);
    if (!oki) atomicAnd(&oki_s, 0);
    __syncthreads();
    if (threadIdx.x == 0) g_mask_mode = okf_s ? 2 : (oki_s ? 1 : 0);
}
__device__ __forceinline__ bool mask_at(const void* m, int i, int mode)
{
    if (mode == 1) return ((const int*)m)[i] != 0;
    if (mode == 2) return ((const float*)m)[i] != 0.f;
    return ((const unsigned char*)m)[i] != 0;
}

// ---------------- LayerNorm -> fp16 --------------------------------------------
__global__ __launch_bounds__(256)
void ln_hf(const float* __restrict__ in, const float* __restrict__ g,
           const float* __restrict__ b, hf* __restrict__ oh, int cols)
{
    __shared__ float r1[256], r2[256];
    long row = blockIdx.x;
    const float* p = in + row * cols;
    hf* ph = oh + row * cols;
    int tid = threadIdx.x;
    float s = 0.f, s2 = 0.f;
    for (int c = tid; c < cols; c += 256) { float v = p[c]; s += v; s2 += v * v; }
    r1[tid] = s; r2[tid] = s2; __syncthreads();
    for (int st = 128; st > 0; st >>= 1) {
        if (tid < st) { r1[tid] += r1[tid + st]; r2[tid] += r2[tid + st]; }
        __syncthreads();
    }
    float mu  = r1[0] / cols;
    float var = r2[0] / cols - mu * mu;
    float inv = rsqrtf(var + 1e-5f);
    for (int c = tid; c < cols; c += 256)
        ph[c] = __float2half((p[c] - mu) * inv * g[c] + b[c]);
}

// ---------------- dual softmax (fp16 sim, fp16 outputs) ------------------------
__global__ __launch_bounds__(256)
void softmax_row(const hf* __restrict__ sim, hf* __restrict__ attn,
                 const void* __restrict__ mask, const void* __restrict__ cmask)
{
    __shared__ float buf[MM_];
    __shared__ float red[256];
    int mode = g_mask_mode;
    long row = blockIdx.x;
    int i = (int)(row % Nn), bh = (int)(row / Nn), b = bh / Hh;
    const hf* src = sim  + row * (long)MM_;
    hf*       dst = attn + row * (long)MM_;
    int tid = threadIdx.x;
    bool mi = mask_at(mask, b * Nn + i, mode);
    float lmax = -3.402823466e38f;
    for (int j = tid; j < MM_; j += 256) {
        bool mj = mask_at(cmask, b * MM_ + j, mode);
        float vv = (mi && mj) ? __half2float(src[j]) : -3.402823466e38f;
        buf[j] = vv; lmax = fmaxf(lmax, vv);
    }
    red[tid] = lmax; __syncthreads();
    for (int s = 128; s > 0; s >>= 1) {
        if (tid < s) red[tid] = fmaxf(red[tid], red[tid + s]);
        __syncthreads();
    }
    float rmax = red[0]; __syncthreads();
    float lsum = 0.f;
    for (int j = tid; j < MM_; j += 256) { float e = expf(buf[j] - rmax); buf[j] = e; lsum += e; }
    red[tid] = lsum; __syncthreads();
    for (int s = 128; s > 0; s >>= 1) {
        if (tid < s) red[tid] += red[tid + s];
        __syncthreads();
    }
    float inv = 1.f / red[0];
    for (int j = tid; j < MM_; j += 256) dst[j] = __float2half(buf[j] * inv);
}

__global__ __launch_bounds__(256)
void softmax_col(const hf* __restrict__ sim, hf* __restrict__ cattn,
                 const void* __restrict__ mask, const void* __restrict__ cmask)
{
    __shared__ float sm[8][32], ss[8][32];
    int mode = g_mask_mode;
    int z = blockIdx.y, b = z / Hh;
    int c = threadIdx.x & 31, g = threadIdx.x >> 5;
    int j = blockIdx.x * 32 + c;
    const hf* base = sim   + (long)z * Nn * MM_;
    hf*       outb = cattn + (long)z * Nn * MM_;
    bool mj = mask_at(cmask, b * MM_ + j, mode);
    float m = -3.402823466e38f, s = 0.f;
    for (int i = g; i < Nn; i += 8) {
        bool mi = mask_at(mask, b * Nn + i, mode);
        float vv = (mj && mi) ? __half2float(base[(long)i * MM_ + j]) : -3.402823466e38f;
        if (vv > m) { s = s * expf(m - vv) + 1.f; m = vv; }
        else        { s += expf(vv - m); }
    }
    sm[g][c] = m; ss[g][c] = s; __syncthreads();
    if (g == 0) {
        float Ml = sm[0][c], Sl = ss[0][c];
        #pragma unroll
        for (int t = 1; t < 8; t++) {
            float mt = sm[t][c], st = ss[t][c];
            float nm = fmaxf(Ml, mt);
            Sl = Sl * expf(Ml - nm) + st * expf(mt - nm);
            Ml = nm;
        }
        sm[0][c] = Ml; ss[0][c] = 1.f / Sl;
    }
    __syncthreads();
    float Mg = sm[0][c], inv = ss[0][c];
    for (int i = g; i < Nn; i += 8) {
        bool mi = mask_at(mask, b * Nn + i, mode);
        float vv = (mj && mi) ? __half2float(base[(long)i * MM_ + j]) : -3.402823466e38f;
        outb[(long)i * MM_ + j] = __float2half(expf(vv - Mg) * inv);
    }
}

// ---------------- weight transpose -> fp16 -------------------------------------
__global__ __launch_bounds__(256)
void wt_prep(const float* __restrict__ W, hf* __restrict__ Th, int K, int N)
{
    __shared__ float t[32][33];
    int n0 = blockIdx.x * 32, k0 = blockIdx.y * 32;
    int tx = threadIdx.x & 31, ty = threadIdx.x >> 5;
    #pragma unroll
    for (int i = 0; i < 4; i++)
        t[ty + i * 8][tx] = W[(long)(k0 + ty + i * 8) * N + n0 + tx];
    __syncthreads();
    #pragma unroll
    for (int i = 0; i < 4; i++)
        Th[(long)(n0 + ty + i * 8) * K + k0 + tx] = __float2half(t[tx][ty + i * 8]);
}

// ---------------- fp16 WMMA GEMM, 3-stage cp.async ------------------------------
// C = alpha * op(A) @ op(B); A [M,K] (or [K,M] if AC), B [K,N] (or [N,K] if BC).
// EPI: 1 = fp16 out (alpha); 2 = f32 + bias + res; 3 = GELU(v+bias) -> fp16.
__device__ __forceinline__ void cpab(uint32_t s, const void* g)
{ asm volatile("cp.async.cg.shared.global [%0], [%1], 16;\n" :: "r"(s), "l"(g)); }

template<int BM, int BN, bool AC, bool BC, int EPI>
__global__ __launch_bounds__(256)
void ghf(const hf* __restrict__ A, int lda, long aO, long aI,
         const hf* __restrict__ Bm, int ldb, long bO, long bI,
         float* __restrict__ C, hf* __restrict__ Cb,
         int ldc, long cO, long cI,
         const float* __restrict__ bias, const float* __restrict__ res, int ldr,
         int K, float alpha, int HHd)
{
    constexpr int BK   = 32;
    constexpr int LDAS = AC ? BM + 8 : BK + 8;
    constexpr int AEL  = AC ? BK * LDAS : BM * LDAS;
    constexpr int LDBS = BC ? BK + 8 : BN + 8;
    constexpr int BEL  = BC ? BN * LDBS : BK * LDBS;
    constexpr int SEL  = AEL + BEL;
    constexpr int WRM  = (BN == 128) ? 2 : 4;
    constexpr int WRN  = 8 / WRM;
    constexpr int TM   = BM / WRM, TN = BN / WRN;
    constexpr int FM   = TM / 16, FN = TN / 16;

    extern __shared__ hf smh_[];
    uint32_t sb0;
    asm("{ .reg .u64 t; cvta.to.shared.u64 t, %1; cvt.u32.u64 %0, t; }"
        : "=r"(sb0) : "l"(smh_));

    int z = blockIdx.z, zo = z / HHd, zi = z % HHd;
    A  += (long)zo * aO + (long)zi * aI;
    Bm += (long)zo * bO + (long)zi * bI;
    long m0 = (long)blockIdx.y * BM, n0 = (long)blockIdx.x * BN;
    int tid = threadIdx.x, warp = tid >> 5;
    int wm0 = (warp % WRM) * TM, wn0 = (warp / WRM) * TN;

    auto load_stage = [&](int s, int kt) {
        uint32_t base = sb0 + (uint32_t)(s * SEL * 2);
        int kb = kt * BK;
        if (!AC) {
            constexpr int C8 = BK / 8, TOT = BM * C8;
            for (int idx = tid; idx < TOT; idx += 256) {
                int r = idx / C8, c = idx % C8;
                cpab(base + (uint32_t)((r * LDAS + c * 8) * 2),
                     A + (m0 + r) * (long)lda + kb + c * 8);
            }
        } else {
            constexpr int C8 = BM / 8, TOT = BK * C8;
            for (int idx = tid; idx < TOT; idx += 256) {
                int k = idx / C8, mc = idx % C8;
                cpab(base + (uint32_t)((k * LDAS + mc * 8) * 2),
                     A + (long)(kb + k) * lda + m0 + mc * 8);
            }
        }
        if (BC) {
            constexpr int C8 = BK / 8, TOT = BN * C8;
            for (int idx = tid; idx < TOT; idx += 256) {
                int n = idx / C8, c = idx % C8;
                cpab(base + (uint32_t)((AEL + n * LDBS + c * 8) * 2),
                     Bm + (n0 + n) * (long)ldb + kb + c * 8);
            }
        } else {
            constexpr int C8 = BN / 8, TOT = BK * C8;
            for (int idx = tid; idx < TOT; idx += 256) {
                int k = idx / C8, c = idx % C8;
                cpab(base + (uint32_t)((AEL + k * LDBS + c * 8) * 2),
                     Bm + (long)(kb + k) * ldb + n0 + c * 8);
            }
        }
        asm volatile("cp.async.commit_group;\n");
    };

    using ALay = typename std::conditional<AC, wmma::col_major, wmma::row_major>::type;
    using BLay = typename std::conditional<BC, wmma::col_major, wmma::row_major>::type;
    wmma::fragment<wmma::accumulator, 16, 16, 16, float> fc[FM][FN];
    #pragma unroll
    for (int i = 0; i < FM; i++)
        #pragma unroll
        for (int j = 0; j < FN; j++)
            wmma::fill_fragment(fc[i][j], 0.f);

    int T = K / BK;
    load_stage(0, 0);
    if (T > 1) load_stage(1, 1);

    for (int kt = 0; kt < T; kt++) {
        if (kt + 1 < T) asm volatile("cp.async.wait_group 1;\n");
        else            asm volatile("cp.async.wait_group 0;\n");
        __syncthreads();
        if (kt + 2 < T) load_stage((kt + 2) % 3, kt + 2);

        const hf* st  = smh_ + (kt % 3) * SEL;
        const hf* sA  = st;
        const hf* sB  = st + AEL;

        #pragma unroll
        for (int kk = 0; kk < BK; kk += 16) {
            wmma::fragment<wmma::matrix_a, 16, 16, 16, hf, ALay> fa[FM];
            wmma::fragment<wmma::matrix_b, 16, 16, 16, hf, BLay> fb[FN];
            #pragma unroll
            for (int i = 0; i < FM; i++) {
                const hf* ap = AC ? (sA + kk * LDAS + wm0 + i * 16)
                                  : (sA + (wm0 + i * 16) * LDAS + kk);
                wmma::load_matrix_sync(fa[i], ap, LDAS);
            }
            #pragma unroll
            for (int j = 0; j < FN; j++) {
                const hf* bp = BC ? (sB + (wn0 + j * 16) * LDBS + kk)
                                  : (sB + kk * LDBS + wn0 + j * 16);
                wmma::load_matrix_sync(fb[j], bp, LDBS);
            }
            #pragma unroll
            for (int i = 0; i < FM; i++)
                #pragma unroll
                for (int j = 0; j < FN; j++)
                    wmma::mma_sync(fc[i][j], fa[i], fb[j], fc[i][j]);
        }
    }

    __syncthreads();
    float* sC = (float*)smh_;
    constexpr int LDCS = BN + 4;
    #pragma unroll
    for (int i = 0; i < FM; i++)
        #pragma unroll
        for (int j = 0; j < FN; j++)
            wmma::store_matrix_sync(sC + (wm0 + i * 16) * LDCS + wn0 + j * 16,
                                    fc[i][j], LDCS, wmma::mem_row_major);
    __syncthreads();
    constexpr int NB4 = BN / 4;
    for (int idx = tid; idx < BM * NB4; idx += 256) {
        int r = idx / NB4, c4 = (idx % NB4) * 4;
        long gm = m0 + r, gn = n0 + c4;
        long cb = (long)zo * cO + (long)zi * cI;
        float v0 = sC[r * LDCS + c4 + 0], v1 = sC[r * LDCS + c4 + 1];
        float v2 = sC[r * LDCS + c4 + 2], v3 = sC[r * LDCS + c4 + 3];
        if (EPI == 1) {
            __half2 p0 = __floats2half2_rn(v0 * alpha, v1 * alpha);
            __half2 p1 = __floats2half2_rn(v2 * alpha, v3 * alpha);
            ((__half2*)(Cb + cb + gm * ldc + gn))[0] = p0;
            ((__half2*)(Cb + cb + gm * ldc + gn))[1] = p1;
        } else if (EPI == 2) {
            float4 bb = *(const float4*)(bias + gn);
            float4 rr = *(const float4*)(res + gm * (long)ldr + gn);
            float4 o = { v0 + bb.x + rr.x, v1 + bb.y + rr.y,
                         v2 + bb.z + rr.z, v3 + bb.w + rr.w };
            *(float4*)(C + cb + gm * ldc + gn) = o;
        } else {
            float4 bb = *(const float4*)(bias + gn);
            float t0 = v0 + bb.x, t1 = v1 + bb.y, t2 = v2 + bb.z, t3 = v3 + bb.w;
            t0 = 0.5f * t0 * (1.f + erff(t0 * 0.7071067811865476f));
            t1 = 0.5f * t1 * (1.f + erff(t1 * 0.7071067811865476f));
            t2 = 0.5f * t2 * (1.f + erff(t2 * 0.7071067811865476f));
            t3 = 0.5f * t3 * (1.f + erff(t3 * 0.7071067811865476f));
            __half2 p0 = __floats2half2_rn(t0, t1);
            __half2 p1 = __floats2half2_rn(t2, t3);
            ((__half2*)(Cb + gm * ldc + gn))[0] = p0;
            ((__half2*)(Cb + gm * ldc + gn))[1] = p1;
        }
    }
}

static constexpr size_t gsm(int BM, int BN, bool AC, bool BC)
{
    int LDAS = AC ? BM + 8 : 40;
    int AEL  = AC ? 32 * LDAS : BM * LDAS;
    int LDBS = BC ? 40 : BN + 8;
    int BEL  = BC ? BN * LDBS : 32 * LDBS;
    size_t pipe = 3u * 2u * (size_t)(AEL + BEL);
    size_t epi  = 4u * (size_t)BM * (BN + 4);
    return pipe > epi ? pipe : epi;
}

#define LGH(BM, BN, AC, BC, EPI, grid, ...)                                      \
    do {                                                                         \
        auto kfn = ghf<BM, BN, AC, BC, EPI>;                                     \
        size_t smb = gsm(BM, BN, AC, BC);                                        \
        cudaFuncSetAttribute(kfn, cudaFuncAttributeMaxDynamicSharedMemorySize, (int)smb); \
        kfn<<<grid, 256, smb>>>(__VA_ARGS__);                                    \
    } while (0)

// ---------------- host ----------------------------------------------------------
extern "C" void kernel_launch(void* const* d_in, const int* in_sizes, int n_in,
                              void* d_out, int out_size)
{
    (void)in_sizes; (void)n_in; (void)out_size;
    const float* x      = (const float*)d_in[0];
    const float* ctx    = (const float*)d_in[1];
    const void*  mask   = d_in[2];
    const void*  cmask  = d_in[3];
    const float* ln_x_g = (const float*)d_in[4];
    const float* ln_x_b = (const float*)d_in[5];
    const float* ln_c_g = (const float*)d_in[6];
    const float* ln_c_b = (const float*)d_in[7];
    const float* W_qk   = (const float*)d_in[8];
    const float* W_v    = (const float*)d_in[9];
    const float* Wc_qk  = (const float*)d_in[10];
    const float* Wc_v   = (const float*)d_in[11];
    const float* W_out  = (const float*)d_in[12];
    const float* b_out  = (const float*)d_in[13];
    const float* Wc_out = (const float*)d_in[14];
    const float* bc_out = (const float*)d_in[15];
    const float* ff_g   = (const float*)d_in[16];
    const float* ff_b   = (const float*)d_in[17];
    const float* ff_w1  = (const float*)d_in[18];
    const float* ff_b1  = (const float*)d_in[19];
    const float* ff_w2  = (const float*)d_in[20];
    const float* ff_b2  = (const float*)d_in[21];
    const float* cff_g  = (const float*)d_in[22];
    const float* cff_b  = (const float*)d_in[23];
    const float* cff_w1 = (const float*)d_in[24];
    const float* cff_b1 = (const float*)d_in[25];
    const float* cff_w2 = (const float*)d_in[26];
    const float* cff_b2 = (const float*)d_in[27];
    float* outp = (float*)d_out;

    float *x1, *c1;
    hf *simb, *attn, *cattn, *qk, *v, *cqk, *cv, *out, *cout;
    hf *xn, *cn, *hb, *wph, *woh, *f1h, *f2h;
    cudaGetSymbolAddress((void**)&x1,    g_x1);
    cudaGetSymbolAddress((void**)&c1,    g_c1);
    cudaGetSymbolAddress((void**)&simb,  g_simb);
    cudaGetSymbolAddress((void**)&attn,  g_attn);
    cudaGetSymbolAddress((void**)&cattn, g_cattn);
    cudaGetSymbolAddress((void**)&qk,    g_qk);
    cudaGetSymbolAddress((void**)&v,     g_v);
    cudaGetSymbolAddress((void**)&cqk,   g_cqk);
    cudaGetSymbolAddress((void**)&cv,    g_cv);
    cudaGetSymbolAddress((void**)&out,   g_out);
    cudaGetSymbolAddress((void**)&cout,  g_cout);
    cudaGetSymbolAddress((void**)&xn,    g_xn);
    cudaGetSymbolAddress((void**)&cn,    g_cn);
    cudaGetSymbolAddress((void**)&hb,    g_hb);
    cudaGetSymbolAddress((void**)&wph,   g_wph);
    cudaGetSymbolAddress((void**)&woh,   g_woh);
    cudaGetSymbolAddress((void**)&f1h,   g_f1h);
    cudaGetSymbolAddress((void**)&f2h,   g_f2h);

    const float SCALE = 0.125f;
    const long PW = (long)INNERi * Dd;
    const long FW = (long)FFDf * Dd;
    const float* nf = nullptr;
    hf* nh = nullptr;

    detect_mask_mode<<<1, 256>>>((const float*)mask, (Bb * Nn) / 4);
    wt_prep<<<dim3(INNERi / 32, Dd / 32), 256>>>(W_qk,  wph + 0 * PW, Dd, INNERi);
    wt_prep<<<dim3(INNERi / 32, Dd / 32), 256>>>(W_v,   wph + 1 * PW, Dd, INNERi);
    wt_prep<<<dim3(INNERi / 32, Dd / 32), 256>>>(Wc_qk, wph + 2 * PW, Dd, INNERi);
    wt_prep<<<dim3(INNERi / 32, Dd / 32), 256>>>(Wc_v,  wph + 3 * PW, Dd, INNERi);
    wt_prep<<<dim3(Dd / 32, INNERi / 32), 256>>>(W_out,  woh + 0 * PW, INNERi, Dd);
    wt_prep<<<dim3(Dd / 32, INNERi / 32), 256>>>(Wc_out, woh + 1 * PW, INNERi, Dd);
    wt_prep<<<dim3(FFDf / 32, Dd / 32), 256>>>(ff_w1,  f1h + 0 * FW, Dd, FFDf);
    wt_prep<<<dim3(FFDf / 32, Dd / 32), 256>>>(cff_w1, f1h + 1 * FW, Dd, FFDf);
    wt_prep<<<dim3(Dd / 32, FFDf / 32), 256>>>(ff_w2,  f2h + 0 * FW, FFDf, Dd);
    wt_prep<<<dim3(Dd / 32, FFDf / 32), 256>>>(cff_w2, f2h + 1 * FW, FFDf, Dd);

    ln_hf<<<Bb * Nn,  256>>>(x,   ln_x_g, ln_x_b, xn, Dd);
    ln_hf<<<Bb * MM_, 256>>>(ctx, ln_c_g, ln_c_b, cn, Dd);

    // projections: 128x128 tiles, fp16 out
    LGH(128, 128, false, true, 1, dim3(INNERi / 128, Bb * Nn / 128, 1),
        xn, Dd, 0, 0, wph + 0 * PW, Dd, 0, 0,
        (float*)nullptr, qk, INNERi, 0, 0, nf, nf, 0, Dd, 1.f, 1);
    LGH(128, 128, false, true, 1, dim3(INNERi / 128, Bb * Nn / 128, 1),
        xn, Dd, 0, 0, wph + 1 * PW, Dd, 0, 0,
        (float*)nullptr, v, INNERi, 0, 0, nf, nf, 0, Dd, 1.f, 1);
    LGH(128, 128, false, true, 1, dim3(INNERi / 128, Bb * MM_ / 128, 1),
        cn, Dd, 0, 0, wph + 2 * PW, Dd, 0, 0,
        (float*)nullptr, cqk, INNERi, 0, 0, nf, nf, 0, Dd, 1.f, 1);
    LGH(128, 128, false, true, 1, dim3(INNERi / 128, Bb * MM_ / 128, 1),
        cn, Dd, 0, 0, wph + 3 * PW, Dd, 0, 0,
        (float*)nullptr, cv, INNERi, 0, 0, nf, nf, 0, Dd, 1.f, 1);

    // sim = qk @ cqk^T * SCALE -> fp16
    LGH(128, 128, false, true, 1, dim3(MM_ / 128, Nn / 128, Bb * Hh),
        qk, INNERi, (long)Nn * INNERi, DHd,
        cqk, INNERi, (long)MM_ * INNERi, DHd,
        (float*)nullptr, simb, MM_, (long)Hh * Nn * MM_, (long)Nn * MM_,
        nf, nf, 0, DHd, SCALE, Hh);

    softmax_row<<<Bb * Hh * Nn, 256>>>(simb, attn, mask, cmask);
    softmax_col<<<dim3(MM_ / 32, Bb * Hh), 256>>>(simb, cattn, mask, cmask);

    // PV: 128x64 tiles
    LGH(128, 64, false, false, 1, dim3(1, Nn / 128, Bb * Hh),
        attn, MM_, (long)Hh * Nn * MM_, (long)Nn * MM_,
        cv, INNERi, (long)MM_ * INNERi, DHd,
        (float*)nullptr, out, INNERi, (long)Nn * INNERi, DHd,
        nf, nf, 0, MM_, 1.f, Hh);
    LGH(128, 64, true, false, 1, dim3(1, MM_ / 128, Bb * Hh),
        cattn, MM_, (long)Hh * Nn * MM_, (long)Nn * MM_,
        v, INNERi, (long)Nn * INNERi, DHd,
        (float*)nullptr, cout, INNERi, (long)MM_ * INNERi, DHd,
        nf, nf, 0, Nn, 1.f, Hh);

    // out-proj + residual (f32)
    LGH(128, 128, false, true, 2, dim3(Dd / 128, Bb * Nn / 128, 1),
        out, INNERi, 0, 0, woh + 0 * PW, INNERi, 0, 0,
        x1, nh, Dd, 0, 0, b_out, x, Dd, INNERi, 1.f, 1);
    LGH(128, 128, false, true, 2, dim3(Dd / 128, Bb * MM_ / 128, 1),
        cout, INNERi, 0, 0, woh + 1 * PW, INNERi, 0, 0,
        c1, nh, Dd, 0, 0, bc_out, ctx, Dd, INNERi, 1.f, 1);

    // FFN x-side (fp16)
    ln_hf<<<Bb * Nn, 256>>>(x1, ff_g, ff_b, xn, Dd);
    LGH(128, 128, false, true, 3, dim3(FFDf / 128, Bb * Nn / 128, 1),
        xn, Dd, 0, 0, f1h + 0 * FW, Dd, 0, 0,
        (float*)nullptr, hb, FFDf, 0, 0, ff_b1, nf, 0, Dd, 1.f, 1);
    LGH(128, 128, false, true, 2, dim3(Dd / 128, Bb * Nn / 128, 1),
        hb, FFDf, 0, 0, f2h + 0 * FW, FFDf, 0, 0,
        outp, nh, Dd, 0, 0, ff_b2, x1, Dd, FFDf, 1.f, 1);

    // FFN context-side
    ln_hf<<<Bb * MM_, 256>>>(c1, cff_g, cff_b, cn, Dd);
    LGH(128, 128, false, true, 3, dim3(FFDf / 128, Bb * MM_ / 128, 1),
        cn, Dd, 0, 0, f1h + 1 * FW, Dd, 0, 0,
        (float*)nullptr, hb, FFDf, 0, 0, cff_b1, nf, 0, Dd, 1.f, 1);
    LGH(128, 128, false, true, 2, dim3(Dd / 128, Bb * MM_ / 128, 1),
        hb, FFDf, 0, 0, f2h + 1 * FW, FFDf, 0, 0,
        outp + (long)Bb * Nn * Dd, nh, Dd, 0, 0, cff_b2, c1, Dd, FFDf, 1.f, 1);
}

// round 13
// speedup vs baseline: 2.9670x; 1.6904x over previous
#include <cuda_runtime.h>
#include <cuda_fp16.h>
#include <mma.h>
#include <math.h>
#include <cstdint>

using namespace nvcuda;
typedef __half hf;

#define Bb 2
#define Nn 2048
#define MM_ 2048
#define Dd 1024
#define Hh 8
#define DHd 64
#define INNERi 512
#define FFDf 4096

#define BND  (Bb*Nn*Dd)        // 4,194,304
#define BNI  (Bb*Nn*INNERi)    // 2,097,152
#define BNF  (Bb*Nn*FFDf)      // 16,777,216
#define DW   (Dd*INNERi)       // 524,288
#define DF   ((long)Dd*FFDf)   // 4,194,304

// ---------------- scratch ----------------------------------------------------
__device__ __align__(256) float g_x1c [2*BND];     // x1 | c1
__device__ __align__(256) float g_resin[2*BND];    // x | ctx (residual concat)
__device__ __align__(256) float g_bo[2*Dd];        // b_out | bc_out
__device__ __align__(256) float g_b1[2*FFDf];      // ff_b1 | cff_b1
__device__ __align__(256) float g_b2[2*Dd];        // ff_b2 | cff_b2
__device__ __align__(256) hf g_simb [Bb*Hh*Nn*MM_];
__device__ __align__(256) hf g_attn [Bb*Hh*Nn*MM_];
__device__ __align__(256) hf g_cattn[Bb*Hh*Nn*MM_];
__device__ __align__(256) hf g_qkv[4*BNI];         // qk | v | cqk | cv
__device__ __align__(256) hf g_oc [2*BNI];         // out | cout
__device__ __align__(256) hf g_xc [2*BND];         // xn | cn (LN outputs, reused)
__device__ __align__(256) hf g_hb [2*BNF];         // FFN hidden (both sides)
__device__ __align__(256) hf g_wp [4*DW];          // W_qk|W_v|Wc_qk|Wc_v fp16 [K,N]
__device__ __align__(256) hf g_wo [2*DW];          // W_out|Wc_out
__device__ __align__(256) hf g_f1 [2*DF];          // ff_w1|cff_w1
__device__ __align__(256) hf g_f2 [2*DF];          // ff_w2|cff_w2
__device__ int g_mask_mode;

// ---------------- f32 -> fp16 convert (no transpose) ---------------------------
__global__ __launch_bounds__(256)
void convh(const float4* __restrict__ in, __half2* __restrict__ out, int n4)
{
    for (int i = blockIdx.x * 256 + threadIdx.x; i < n4; i += gridDim.x * 256) {
        float4 v = in[i];
        out[2 * i]     = __floats2half2_rn(v.x, v.y);
        out[2 * i + 1] = __floats2half2_rn(v.z, v.w);
    }
}

// ---------------- mask detection ---------------------------------------------
__global__ void detect_mask_mode(const float* __restrict__ fp, int n4)
{
    __shared__ int okf_s, oki_s;
    if (threadIdx.x == 0) { okf_s = 1; oki_s = 1; }
    __syncthreads();
    const int* ip = (const int*)fp;
    bool okf = true, oki = true;
    for (int i = threadIdx.x; i < n4; i += 256) {
        float fv = fp[i]; okf = okf && (fv == 0.f || fv == 1.f);
        int   iv = ip[i]; oki = oki && (iv == 0 || iv == 1);
    }
    if (!okf) atomicAnd(&okf_s, 0);
    if (!oki) atomicAnd(&oki_s, 0);
    __syncthreads();
    if (threadIdx.x == 0) g_mask_mode = okf_s ? 2 : (oki_s ? 1 : 0);
}
__device__ __forceinline__ bool mask_at(const void* m, int i, int mode)
{
    if (mode == 1) return ((const int*)m)[i] != 0;
    if (mode == 2) return ((const float*)m)[i] != 0.f;
    return ((const unsigned char*)m)[i] != 0;
}

// ---------------- LayerNorm -> fp16 --------------------------------------------
__global__ __launch_bounds__(256)
void ln_hf(const float* __restrict__ in, const float* __restrict__ g,
           const float* __restrict__ b, hf* __restrict__ oh, int cols)
{
    __shared__ float r1[256], r2[256];
    long row = blockIdx.x;
    const float* p = in + row * cols;
    hf* ph = oh + row * cols;
    int tid = threadIdx.x;
    float s = 0.f, s2 = 0.f;
    for (int c = tid; c < cols; c += 256) { float v = p[c]; s += v; s2 += v * v; }
    r1[tid] = s; r2[tid] = s2; __syncthreads();
    for (int st = 128; st > 0; st >>= 1) {
        if (tid < st) { r1[tid] += r1[tid + st]; r2[tid] += r2[tid + st]; }
        __syncthreads();
    }
    float mu  = r1[0] / cols;
    float var = r2[0] / cols - mu * mu;
    float inv = rsqrtf(var + 1e-5f);
    for (int c = tid; c < cols; c += 256)
        ph[c] = __float2half((p[c] - mu) * inv * g[c] + b[c]);
}

// ---------------- dual softmax --------------------------------------------------
__global__ __launch_bounds__(256)
void softmax_row(const hf* __restrict__ sim, hf* __restrict__ attn,
                 const void* __restrict__ mask, const void* __restrict__ cmask)
{
    __shared__ float buf[MM_];
    __shared__ float red[256];
    int mode = g_mask_mode;
    long row = blockIdx.x;
    int i = (int)(row % Nn), bh = (int)(row / Nn), b = bh / Hh;
    const hf* src = sim  + row * (long)MM_;
    hf*       dst = attn + row * (long)MM_;
    int tid = threadIdx.x;
    bool mi = mask_at(mask, b * Nn + i, mode);
    float lmax = -3.402823466e38f;
    for (int j = tid; j < MM_; j += 256) {
        bool mj = mask_at(cmask, b * MM_ + j, mode);
        float vv = (mi && mj) ? __half2float(src[j]) : -3.402823466e38f;
        buf[j] = vv; lmax = fmaxf(lmax, vv);
    }
    red[tid] = lmax; __syncthreads();
    for (int s = 128; s > 0; s >>= 1) {
        if (tid < s) red[tid] = fmaxf(red[tid], red[tid + s]);
        __syncthreads();
    }
    float rmax = red[0]; __syncthreads();
    float lsum = 0.f;
    for (int j = tid; j < MM_; j += 256) { float e = expf(buf[j] - rmax); buf[j] = e; lsum += e; }
    red[tid] = lsum; __syncthreads();
    for (int s = 128; s > 0; s >>= 1) {
        if (tid < s) red[tid] += red[tid + s];
        __syncthreads();
    }
    float inv = 1.f / red[0];
    for (int j = tid; j < MM_; j += 256) dst[j] = __float2half(buf[j] * inv);
}

__global__ __launch_bounds__(256)
void softmax_col(const hf* __restrict__ sim, hf* __restrict__ cattn,
                 const void* __restrict__ mask, const void* __restrict__ cmask)
{
    __shared__ float sm[8][32], ss[8][32];
    int mode = g_mask_mode;
    int z = blockIdx.y, b = z / Hh;
    int c = threadIdx.x & 31, g = threadIdx.x >> 5;
    int j = blockIdx.x * 32 + c;
    const hf* base = sim   + (long)z * Nn * MM_;
    hf*       outb = cattn + (long)z * Nn * MM_;
    bool mj = mask_at(cmask, b * MM_ + j, mode);
    float m = -3.402823466e38f, s = 0.f;
    for (int i = g; i < Nn; i += 8) {
        bool mi = mask_at(mask, b * Nn + i, mode);
        float vv = (mj && mi) ? __half2float(base[(long)i * MM_ + j]) : -3.402823466e38f;
        if (vv > m) { s = s * expf(m - vv) + 1.f; m = vv; }
        else        { s += expf(vv - m); }
    }
    sm[g][c] = m; ss[g][c] = s; __syncthreads();
    if (g == 0) {
        float Ml = sm[0][c], Sl = ss[0][c];
        #pragma unroll
        for (int t = 1; t < 8; t++) {
            float mt = sm[t][c], st = ss[t][c];
            float nm = fmaxf(Ml, mt);
            Sl = Sl * expf(Ml - nm) + st * expf(mt - nm);
            Ml = nm;
        }
        sm[0][c] = Ml; ss[0][c] = 1.f / Sl;
    }
    __syncthreads();
    float Mg = sm[0][c], inv = ss[0][c];
    for (int i = g; i < Nn; i += 8) {
        bool mi = mask_at(mask, b * Nn + i, mode);
        float vv = (mj && mi) ? __half2float(base[(long)i * MM_ + j]) : -3.402823466e38f;
        outb[(long)i * MM_ + j] = __float2half(expf(vv - Mg) * inv);
    }
}

// ---------------- fp16 WMMA GEMM, BK=64, 3-stage cp.async ----------------------
// C = alpha * op(A) @ op(B); A [M,K] (or [K,M] if AC), B [K,N] (or [N,K] if BC).
// Batched: z -> zo=z/HHd, zi=z%HHd; strides aO/aI, bO/bI, cO/cI, bias biO*zo,
// res reO*zo.  EPI: 1 = fp16 out (alpha); 2 = f32+bias+res; 3 = GELU(v+bias)->fp16.
__device__ __forceinline__ void cpab(uint32_t s, const void* g)
{ asm volatile("cp.async.cg.shared.global [%0], [%1], 16;\n" :: "r"(s), "l"(g)); }

template<int BM, int BN, bool AC, bool BC, int EPI>
__global__ __launch_bounds__(256)
void ghf(const hf* __restrict__ A, int lda, long aO, long aI,
         const hf* __restrict__ Bm, int ldb, long bO, long bI,
         float* __restrict__ C, hf* __restrict__ Cb,
         int ldc, long cO, long cI,
         const float* __restrict__ bias, long biO,
         const float* __restrict__ res, int ldr, long reO,
         int K, float alpha, int HHd)
{
    constexpr int BK   = 64;
    constexpr int LDAS = AC ? BM + 8 : BK + 8;
    constexpr int AEL  = AC ? BK * LDAS : BM * LDAS;
    constexpr int LDBS = BC ? BK + 8 : BN + 8;
    constexpr int BEL  = BC ? BN * LDBS : BK * LDBS;
    constexpr int SEL  = AEL + BEL;
    constexpr int WRM  = (BN == 128) ? 2 : 4;
    constexpr int WRN  = 8 / WRM;
    constexpr int TM   = BM / WRM, TN = BN / WRN;
    constexpr int FM   = TM / 16, FN = TN / 16;

    extern __shared__ hf smh_[];
    uint32_t sb0;
    asm("{ .reg .u64 t; cvta.to.shared.u64 t, %1; cvt.u32.u64 %0, t; }"
        : "=r"(sb0) : "l"(smh_));

    int z = blockIdx.z, zo = z / HHd, zi = z % HHd;
    A  += (long)zo * aO + (long)zi * aI;
    Bm += (long)zo * bO + (long)zi * bI;
    long m0 = (long)blockIdx.y * BM, n0 = (long)blockIdx.x * BN;
    int tid = threadIdx.x, warp = tid >> 5;
    int wm0 = (warp % WRM) * TM, wn0 = (warp / WRM) * TN;

    auto load_stage = [&](int s, int kt) {
        uint32_t base = sb0 + (uint32_t)(s * SEL * 2);
        int kb = kt * BK;
        if (!AC) {
            constexpr int C8 = BK / 8, TOT = BM * C8;
            #pragma unroll
            for (int t = 0; t < TOT / 256; t++) {
                int idx = t * 256 + tid;
                int r = idx / C8, c = idx % C8;
                cpab(base + (uint32_t)((r * LDAS + c * 8) * 2),
                     A + (m0 + r) * (long)lda + kb + c * 8);
            }
        } else {
            constexpr int C8 = BM / 8, TOT = BK * C8;
            #pragma unroll
            for (int t = 0; t < TOT / 256; t++) {
                int idx = t * 256 + tid;
                int k = idx / C8, mc = idx % C8;
                cpab(base + (uint32_t)((k * LDAS + mc * 8) * 2),
                     A + (long)(kb + k) * lda + m0 + mc * 8);
            }
        }
        if (BC) {
            constexpr int C8 = BK / 8, TOT = BN * C8;
            #pragma unroll
            for (int t = 0; t < TOT / 256; t++) {
                int idx = t * 256 + tid;
                int n = idx / C8, c = idx % C8;
                cpab(base + (uint32_t)((AEL + n * LDBS + c * 8) * 2),
                     Bm + (n0 + n) * (long)ldb + kb + c * 8);
            }
        } else {
            constexpr int C8 = BN / 8, TOT = BK * C8;
            #pragma unroll
            for (int t = 0; t < TOT / 256; t++) {
                int idx = t * 256 + tid;
                int k = idx / C8, c = idx % C8;
                cpab(base + (uint32_t)((AEL + k * LDBS + c * 8) * 2),
                     Bm + (long)(kb + k) * ldb + n0 + c * 8);
            }
        }
        asm volatile("cp.async.commit_group;\n");
    };

    using ALay = typename std::conditional<AC, wmma::col_major, wmma::row_major>::type;
    using BLay = typename std::conditional<BC, wmma::col_major, wmma::row_major>::type;
    wmma::fragment<wmma::accumulator, 16, 16, 16, float> fc[FM][FN];
    #pragma unroll
    for (int i = 0; i < FM; i++)
        #pragma unroll
        for (int j = 0; j < FN; j++)
            wmma::fill_fragment(fc[i][j], 0.f);

    int T = K / BK;
    load_stage(0, 0);
    if (T > 1) load_stage(1, 1);

    for (int kt = 0; kt < T; kt++) {
        if (kt + 1 < T) asm volatile("cp.async.wait_group 1;\n");
        else            asm volatile("cp.async.wait_group 0;\n");
        __syncthreads();
        if (kt + 2 < T) load_stage((kt + 2) % 3, kt + 2);

        const hf* st = smh_ + (kt % 3) * SEL;
        const hf* sA = st;
        const hf* sB = st + AEL;

        #pragma unroll
        for (int kk = 0; kk < BK; kk += 16) {
            wmma::fragment<wmma::matrix_a, 16, 16, 16, hf, ALay> fa[FM];
            wmma::fragment<wmma::matrix_b, 16, 16, 16, hf, BLay> fb[FN];
            #pragma unroll
            for (int i = 0; i < FM; i++) {
                const hf* ap = AC ? (sA + kk * LDAS + wm0 + i * 16)
                                  : (sA + (wm0 + i * 16) * LDAS + kk);
                wmma::load_matrix_sync(fa[i], ap, LDAS);
            }
            #pragma unroll
            for (int j = 0; j < FN; j++) {
                const hf* bp = BC ? (sB + (wn0 + j * 16) * LDBS + kk)
                                  : (sB + kk * LDBS + wn0 + j * 16);
                wmma::load_matrix_sync(fb[j], bp, LDBS);
            }
            #pragma unroll
            for (int i = 0; i < FM; i++)
                #pragma unroll
                for (int j = 0; j < FN; j++)
                    wmma::mma_sync(fc[i][j], fa[i], fb[j], fc[i][j]);
        }
    }

    __syncthreads();
    float* sC = (float*)smh_;
    constexpr int LDCS = BN + 4;
    #pragma unroll
    for (int i = 0; i < FM; i++)
        #pragma unroll
        for (int j = 0; j < FN; j++)
            wmma::store_matrix_sync(sC + (wm0 + i * 16) * LDCS + wn0 + j * 16,
                                    fc[i][j], LDCS, wmma::mem_row_major);
    __syncthreads();
    constexpr int NB4 = BN / 4;
    long cb = (long)zo * cO + (long)zi * cI;
    const float* bz = bias + (long)zo * biO;
    const float* rz = res  + (long)zo * reO;
    for (int idx = tid; idx < BM * NB4; idx += 256) {
        int r = idx / NB4, c4 = (idx % NB4) * 4;
        long gm = m0 + r, gn = n0 + c4;
        float v0 = sC[r * LDCS + c4 + 0], v1 = sC[r * LDCS + c4 + 1];
        float v2 = sC[r * LDCS + c4 + 2], v3 = sC[r * LDCS + c4 + 3];
        if (EPI == 1) {
            __half2 p0 = __floats2half2_rn(v0 * alpha, v1 * alpha);
            __half2 p1 = __floats2half2_rn(v2 * alpha, v3 * alpha);
            ((__half2*)(Cb + cb + gm * ldc + gn))[0] = p0;
            ((__half2*)(Cb + cb + gm * ldc + gn))[1] = p1;
        } else if (EPI == 2) {
            float4 bb = *(const float4*)(bz + gn);
            float4 rr = *(const float4*)(rz + gm * (long)ldr + gn);
            float4 o = { v0 + bb.x + rr.x, v1 + bb.y + rr.y,
                         v2 + bb.z + rr.z, v3 + bb.w + rr.w };
            *(float4*)(C + cb + gm * ldc + gn) = o;
        } else {
            float4 bb = *(const float4*)(bz + gn);
            float t0 = v0 + bb.x, t1 = v1 + bb.y, t2 = v2 + bb.z, t3 = v3 + bb.w;
            t0 = 0.5f * t0 * (1.f + erff(t0 * 0.7071067811865476f));
            t1 = 0.5f * t1 * (1.f + erff(t1 * 0.7071067811865476f));
            t2 = 0.5f * t2 * (1.f + erff(t2 * 0.7071067811865476f));
            t3 = 0.5f * t3 * (1.f + erff(t3 * 0.7071067811865476f));
            __half2 p0 = __floats2half2_rn(t0, t1);
            __half2 p1 = __floats2half2_rn(t2, t3);
            ((__half2*)(Cb + cb + gm * ldc + gn))[0] = p0;
            ((__half2*)(Cb + cb + gm * ldc + gn))[1] = p1;
        }
    }
}

static constexpr size_t gsm(int BM, int BN, bool AC, bool BC)
{
    int BK = 64;
    int LDAS = AC ? BM + 8 : BK + 8;
    int AEL  = AC ? BK * LDAS : BM * LDAS;
    int LDBS = BC ? BK + 8 : BN + 8;
    int BEL  = BC ? BN * LDBS : BK * LDBS;
    size_t pipe = 3u * 2u * (size_t)(AEL + BEL);
    size_t epi  = 4u * (size_t)BM * (BN + 4);
    return pipe > epi ? pipe : epi;
}

#define LGH(BM, BN, AC, BC, EPI, grid, ...)                                      \
    do {                                                                         \
        auto kfn = ghf<BM, BN, AC, BC, EPI>;                                     \
        size_t smb = gsm(BM, BN, AC, BC);                                        \
        cudaFuncSetAttribute(kfn, cudaFuncAttributeMaxDynamicSharedMemorySize, (int)smb); \
        kfn<<<grid, 256, smb>>>(__VA_ARGS__);                                    \
    } while (0)

// ---------------- host ----------------------------------------------------------
extern "C" void kernel_launch(void* const* d_in, const int* in_sizes, int n_in,
                              void* d_out, int out_size)
{
    (void)in_sizes; (void)n_in; (void)out_size;
    const float* x      = (const float*)d_in[0];
    const float* ctx    = (const float*)d_in[1];
    const void*  mask   = d_in[2];
    const void*  cmask  = d_in[3];
    const float* ln_x_g = (const float*)d_in[4];
    const float* ln_x_b = (const float*)d_in[5];
    const float* ln_c_g = (const float*)d_in[6];
    const float* ln_c_b = (const float*)d_in[7];
    const float* W_qk   = (const float*)d_in[8];
    const float* W_v    = (const float*)d_in[9];
    const float* Wc_qk  = (const float*)d_in[10];
    const float* Wc_v   = (const float*)d_in[11];
    const float* W_out  = (const float*)d_in[12];
    const float* b_out  = (const float*)d_in[13];
    const float* Wc_out = (const float*)d_in[14];
    const float* bc_out = (const float*)d_in[15];
    const float* ff_g   = (const float*)d_in[16];
    const float* ff_b   = (const float*)d_in[17];
    const float* ff_w1  = (const float*)d_in[18];
    const float* ff_b1  = (const float*)d_in[19];
    const float* ff_w2  = (const float*)d_in[20];
    const float* ff_b2  = (const float*)d_in[21];
    const float* cff_g  = (const float*)d_in[22];
    const float* cff_b  = (const float*)d_in[23];
    const float* cff_w1 = (const float*)d_in[24];
    const float* cff_b1 = (const float*)d_in[25];
    const float* cff_w2 = (const float*)d_in[26];
    const float* cff_b2 = (const float*)d_in[27];
    float* outp = (float*)d_out;

    float *x1c, *resin, *bo, *b1, *b2;
    hf *simb, *attn, *cattn, *qkv, *oc, *xc, *hb, *wp, *wo, *f1, *f2;
    cudaGetSymbolAddress((void**)&x1c,   g_x1c);
    cudaGetSymbolAddress((void**)&resin, g_resin);
    cudaGetSymbolAddress((void**)&bo,    g_bo);
    cudaGetSymbolAddress((void**)&b1,    g_b1);
    cudaGetSymbolAddress((void**)&b2,    g_b2);
    cudaGetSymbolAddress((void**)&simb,  g_simb);
    cudaGetSymbolAddress((void**)&attn,  g_attn);
    cudaGetSymbolAddress((void**)&cattn, g_cattn);
    cudaGetSymbolAddress((void**)&qkv,   g_qkv);
    cudaGetSymbolAddress((void**)&oc,    g_oc);
    cudaGetSymbolAddress((void**)&xc,    g_xc);
    cudaGetSymbolAddress((void**)&hb,    g_hb);
    cudaGetSymbolAddress((void**)&wp,    g_wp);
    cudaGetSymbolAddress((void**)&wo,    g_wo);
    cudaGetSymbolAddress((void**)&f1,    g_f1);
    cudaGetSymbolAddress((void**)&f2,    g_f2);

    const float SCALE = 0.125f;
    const float* nf = nullptr;
    hf* nh = nullptr;

    // 0) mask dtype; weight converts (no transpose); concat copies
    detect_mask_mode<<<1, 256>>>((const float*)mask, (Bb * Nn) / 4);
    convh<<<256, 256>>>((const float4*)W_qk,   (__half2*)(wp + 0L * DW), DW / 4);
    convh<<<256, 256>>>((const float4*)W_v,    (__half2*)(wp + 1L * DW), DW / 4);
    convh<<<256, 256>>>((const float4*)Wc_qk,  (__half2*)(wp + 2L * DW), DW / 4);
    convh<<<256, 256>>>((const float4*)Wc_v,   (__half2*)(wp + 3L * DW), DW / 4);
    convh<<<256, 256>>>((const float4*)W_out,  (__half2*)(wo + 0L * DW), DW / 4);
    convh<<<256, 256>>>((const float4*)Wc_out, (__half2*)(wo + 1L * DW), DW / 4);
    convh<<<512, 256>>>((const float4*)ff_w1,  (__half2*)(f1 + 0L * DF), (int)(DF / 4));
    convh<<<512, 256>>>((const float4*)cff_w1, (__half2*)(f1 + 1L * DF), (int)(DF / 4));
    convh<<<512, 256>>>((const float4*)ff_w2,  (__half2*)(f2 + 0L * DF), (int)(DF / 4));
    convh<<<512, 256>>>((const float4*)cff_w2, (__half2*)(f2 + 1L * DF), (int)(DF / 4));
    cudaMemcpyAsync(bo,       b_out,   Dd * 4,   cudaMemcpyDeviceToDevice, 0);
    cudaMemcpyAsync(bo + Dd,  bc_out,  Dd * 4,   cudaMemcpyDeviceToDevice, 0);
    cudaMemcpyAsync(b1,        ff_b1,  FFDf * 4, cudaMemcpyDeviceToDevice, 0);
    cudaMemcpyAsync(b1 + FFDf, cff_b1, FFDf * 4, cudaMemcpyDeviceToDevice, 0);
    cudaMemcpyAsync(b2,       ff_b2,   Dd * 4,   cudaMemcpyDeviceToDevice, 0);
    cudaMemcpyAsync(b2 + Dd,  cff_b2,  Dd * 4,   cudaMemcpyDeviceToDevice, 0);
    cudaMemcpyAsync(resin,        x,   (size_t)BND * 4, cudaMemcpyDeviceToDevice, 0);
    cudaMemcpyAsync(resin + BND,  ctx, (size_t)BND * 4, cudaMemcpyDeviceToDevice, 0);

    // 1) pre-norm -> fp16 (xn | cn contiguous)
    ln_hf<<<Bb * Nn,  256>>>(x,   ln_x_g, ln_x_b, xc, Dd);
    ln_hf<<<Bb * MM_, 256>>>(ctx, ln_c_g, ln_c_b, xc + BND, Dd);

    // 2) all 4 projections in ONE launch (z: 0=qk,1=v,2=cqk,3=cv; zo=z/2 picks xn/cn)
    LGH(128, 128, false, false, 1, dim3(INNERi / 128, Bb * Nn / 128, 4),
        xc, Dd, BND, 0,
        wp, INNERi, 2L * DW, DW,
        (float*)nullptr, qkv, INNERi, 2L * BNI, BNI,
        nf, 0, nf, 0, 0, Dd, 1.f, 2);

    // 3) sim = qk @ cqk^T * SCALE -> fp16 (BC=true activation transpose)
    LGH(128, 128, false, true, 1, dim3(MM_ / 128, Nn / 128, Bb * Hh),
        qkv, INNERi, (long)Nn * INNERi, DHd,
        qkv + 2L * BNI, INNERi, (long)MM_ * INNERi, DHd,
        (float*)nullptr, simb, MM_, (long)Hh * Nn * MM_, (long)Nn * MM_,
        nf, 0, nf, 0, 0, DHd, SCALE, Hh);

    // 4) dual softmax
    softmax_row<<<Bb * Hh * Nn, 256>>>(simb, attn, mask, cmask);
    softmax_col<<<dim3(MM_ / 32, Bb * Hh), 256>>>(simb, cattn, mask, cmask);

    // 5) PV: out = attn @ cv ; cout = cattn^T @ v  (-> oc | oc+BNI)
    LGH(128, 64, false, false, 1, dim3(1, Nn / 128, Bb * Hh),
        attn, MM_, (long)Hh * Nn * MM_, (long)Nn * MM_,
        qkv + 3L * BNI, INNERi, (long)MM_ * INNERi, DHd,
        (float*)nullptr, oc, INNERi, (long)Nn * INNERi, DHd,
        nf, 0, nf, 0, 0, MM_, 1.f, Hh);
    LGH(128, 64, true, false, 1, dim3(1, MM_ / 128, Bb * Hh),
        cattn, MM_, (long)Hh * Nn * MM_, (long)Nn * MM_,
        qkv + 1L * BNI, INNERi, (long)Nn * INNERi, DHd,
        (float*)nullptr, oc + BNI, INNERi, (long)MM_ * INNERi, DHd,
        nf, 0, nf, 0, 0, Nn, 1.f, Hh);

    // 6) out-proj + residual, both sides in ONE launch -> x1 | c1
    LGH(128, 128, false, false, 2, dim3(Dd / 128, Bb * Nn / 128, 2),
        oc, INNERi, BNI, 0,
        wo, Dd, DW, 0,
        x1c, nh, Dd, BND, 0,
        bo, Dd, resin, Dd, BND, INNERi, 1.f, 1);

    // 7) FFN LN both sides -> xc
    ln_hf<<<Bb * Nn,  256>>>(x1c,       ff_g,  ff_b,  xc, Dd);
    ln_hf<<<Bb * MM_, 256>>>(x1c + BND, cff_g, cff_b, xc + BND, Dd);

    // 8) FFN1 both sides (GELU -> fp16)
    LGH(128, 128, false, false, 3, dim3(FFDf / 128, Bb * Nn / 128, 2),
        xc, Dd, BND, 0,
        f1, FFDf, DF, 0,
        (float*)nullptr, hb, FFDf, (long)BNF, 0,
        b1, FFDf, nf, 0, 0, Dd, 1.f, 1);

    // 9) FFN2 both sides -> d_out directly (x-side at 0, c-side at BND)
    LGH(128, 128, false, false, 2, dim3(Dd / 128, Bb * Nn / 128, 2),
        hb, FFDf, (long)BNF, 0,
        f2, Dd, DF, 0,
        outp, nh, Dd, BND, 0,
        b2, Dd, x1c, Dd, BND, FFDf, 1.f, 1);
}